// round 6
// baseline (speedup 1.0000x reference)
#include <cuda_runtime.h>
#include <cstdint>

#define D 128
#define NN_MAX 50000
#define NGRAPH 64
#define NCLASS 16

// ---------------- device scratch (allocation-free) ----------------
__device__ __align__(256) float g_h [NN_MAX * D];
__device__ __align__(256) float g_t [NN_MAX * D];
__device__ __align__(256) float g_m [NN_MAX * D];
__device__ __align__(256) float g_z [NN_MAX * D];
__device__ __align__(256) float g_r [NN_MAX * D];
__device__ __align__(256) float g_ci[NN_MAX * D];
__device__ __align__(256) float g_g [NN_MAX * D];
__device__ __align__(256) float g_cb[3 * D];     // combined biases: z, r, h
__device__ __align__(256) float g_pmax[NGRAPH * D];
__device__ __align__(256) float g_psum[NGRAPH * D];
__device__ __align__(256) float g_cnt [NGRAPH];

__device__ __forceinline__ float sigf(float x) { return 1.0f / (1.0f + __expf(-x)); }

// ---------------- fused multi-output TF32 tensor-core GEMM (cp.async pipelined) ----------------
// modes: 0: out = acc (+bias)   1: out = sigmoid(acc + aux1[idx])
//        2: r = sigmoid(acc+aux1[idx]); out = r*aux2[idx]
//        3: out[idx] += acc     4: g2 = acc+bias[col]; out = aux2*(aux1*sigf(g2)) + (1-aux2)*out
//        5: out = relu(acc + bias)   6: out = acc (+bias), also write to aux2 (second dest)
struct GemmOut {
    const float* W;
    const float* bias;
    const float* aux1;
    const float* aux2;
    float* out;
    int mode;
};
struct GemmParams { GemmOut o[3]; };

__device__ __forceinline__ void epi_apply(const GemmOut& o, size_t idx, int col, float v) {
    switch (o.mode) {
    case 0: if (o.bias) v += o.bias[col]; o.out[idx] = v; break;
    case 1: o.out[idx] = sigf(v + o.aux1[idx]); break;
    case 2: { float r = sigf(v + o.aux1[idx]); o.out[idx] = r * o.aux2[idx]; } break;
    case 3: o.out[idx] += v; break;
    case 4: { float g2 = v + o.bias[col]; float g1 = o.aux1[idx]; float zz = o.aux2[idx];
              o.out[idx] = zz * (g1 * sigf(g2)) + (1.f - zz) * o.out[idx]; } break;
    case 5: v += o.bias[col]; o.out[idx] = fmaxf(v, 0.f); break;
    case 6: if (o.bias) v += o.bias[col]; o.out[idx] = v; ((float*)o.aux2)[idx] = v; break;
    }
}

#define MMA_TF32(c, a, b) \
    asm volatile("mma.sync.aligned.m16n8k8.row.col.f32.tf32.tf32.f32 " \
        "{%0,%1,%2,%3}, {%4,%5,%6,%7}, {%8,%9}, {%0,%1,%2,%3};" \
        : "+f"((c)[0]), "+f"((c)[1]), "+f"((c)[2]), "+f"((c)[3]) \
        : "r"((a)[0]), "r"((a)[1]), "r"((a)[2]), "r"((a)[3]), "r"((b)[0]), "r"((b)[1]))

__device__ __forceinline__ void cp16(void* smem_ptr, const void* gptr, int src_bytes) {
    uint32_t s = (uint32_t)__cvta_generic_to_shared(smem_ptr);
    asm volatile("cp.async.cg.shared.global [%0], [%1], 16, %2;"
                 :: "r"(s), "l"(gptr), "r"(src_bytes));
}

// smem layout (dynamic): As[2][128][36] floats, then Bs[2][32][132] floats
#define AS_STRIDE 36
#define BS_STRIDE 132
#define AS_BUF (128 * AS_STRIDE)
#define BS_BUF (32 * BS_STRIDE)
#define SMEM_FLOATS (2 * AS_BUF + 2 * BS_BUF)
#define GEMM_SMEM_BYTES (SMEM_FLOATS * 4)

template<int NOUT>
__global__ void __launch_bounds__(256) gemm_fused(const float* __restrict__ A, GemmParams p, int N)
{
    extern __shared__ float smem[];
    float* AsBase = smem;                  // [2][128][36]
    float* BsBase = smem + 2 * AS_BUF;     // [2][32][132]

    const int tid  = threadIdx.x;
    const int lane = tid & 31;
    const int wid  = tid >> 5;
    const int wm   = wid >> 2;          // 0..1 -> m offset wm*64
    const int wn   = wid & 3;           // 0..3 -> n offset wn*32
    const int row0 = blockIdx.x * 128;
    const int gid  = lane >> 2;         // groupID 0..7
    const int tig  = lane & 3;          // thread-in-group 0..3

    // per-thread staging coords (raw f32, no cvt: HW reads tf32 bits)
    const int ar = tid >> 3, akg = (tid & 7) * 4;        // + i*32 rows
    const int bk = tid >> 5, bng = (tid & 31) * 4;       // + i*8 k-rows

    for (int o = 0; o < NOUT; o++) {
        const float* __restrict__ W = p.o[o].W;
        float acc[4][4][4];
#pragma unroll
        for (int mf = 0; mf < 4; mf++)
#pragma unroll
            for (int nf = 0; nf < 4; nf++)
#pragma unroll
                for (int q = 0; q < 4; q++) acc[mf][nf][q] = 0.f;

        // stage chunk 0 into buf 0
        {
            float* As = AsBase;
            float* Bs = BsBase;
#pragma unroll
            for (int i = 0; i < 4; i++) {
                int r = ar + i * 32;
                int grow = row0 + r;
                cp16(&As[r * AS_STRIDE + akg], &A[(size_t)grow * D + akg],
                     (grow < N) ? 16 : 0);
            }
#pragma unroll
            for (int i = 0; i < 4; i++) {
                int k = bk + i * 8;
                cp16(&Bs[k * BS_STRIDE + bng], &W[(size_t)k * D + bng], 16);
            }
            asm volatile("cp.async.commit_group;");
        }

#pragma unroll
        for (int kcs = 0; kcs < 4; kcs++) {
            const int buf = kcs & 1;
            // prefetch next chunk into other buffer
            if (kcs + 1 < 4) {
                const int kc = (kcs + 1) * 32;
                float* As = AsBase + (buf ^ 1) * AS_BUF;
                float* Bs = BsBase + (buf ^ 1) * BS_BUF;
#pragma unroll
                for (int i = 0; i < 4; i++) {
                    int r = ar + i * 32;
                    int grow = row0 + r;
                    cp16(&As[r * AS_STRIDE + akg], &A[(size_t)grow * D + kc + akg],
                         (grow < N) ? 16 : 0);
                }
#pragma unroll
                for (int i = 0; i < 4; i++) {
                    int k = bk + i * 8;
                    cp16(&Bs[k * BS_STRIDE + bng], &W[(size_t)(kc + k) * D + bng], 16);
                }
                asm volatile("cp.async.commit_group;");
                asm volatile("cp.async.wait_group 1;");
            } else {
                asm volatile("cp.async.wait_group 0;");
            }
            __syncthreads();

            const uint32_t* Asb = (const uint32_t*)(AsBase + buf * AS_BUF);
            const uint32_t* Bsb = (const uint32_t*)(BsBase + buf * BS_BUF);
#pragma unroll
            for (int k8 = 0; k8 < 4; k8++) {
                const int kb = k8 * 8;
                uint32_t af[4][4];
#pragma unroll
                for (int mf = 0; mf < 4; mf++) {
                    int r = wm * 64 + mf * 16 + gid;
                    af[mf][0] = Asb[r * AS_STRIDE + kb + tig];
                    af[mf][1] = Asb[(r + 8) * AS_STRIDE + kb + tig];
                    af[mf][2] = Asb[r * AS_STRIDE + kb + tig + 4];
                    af[mf][3] = Asb[(r + 8) * AS_STRIDE + kb + tig + 4];
                }
                uint32_t bf[4][2];
#pragma unroll
                for (int nf = 0; nf < 4; nf++) {
                    int n = wn * 32 + nf * 8 + gid;
                    bf[nf][0] = Bsb[(kb + tig) * BS_STRIDE + n];
                    bf[nf][1] = Bsb[(kb + tig + 4) * BS_STRIDE + n];
                }
#pragma unroll
                for (int mf = 0; mf < 4; mf++)
#pragma unroll
                    for (int nf = 0; nf < 4; nf++)
                        MMA_TF32(acc[mf][nf], af[mf], bf[nf]);
            }
            __syncthreads();
        }

        // epilogue
        const GemmOut& po = p.o[o];
#pragma unroll
        for (int mf = 0; mf < 4; mf++) {
            int ra = row0 + wm * 64 + mf * 16 + gid;
            int rb = ra + 8;
#pragma unroll
            for (int nf = 0; nf < 4; nf++) {
                int c0 = wn * 32 + nf * 8 + tig * 2;
                if (ra < N) {
                    epi_apply(po, (size_t)ra * D + c0,     c0,     acc[mf][nf][0]);
                    epi_apply(po, (size_t)ra * D + c0 + 1, c0 + 1, acc[mf][nf][1]);
                }
                if (rb < N) {
                    epi_apply(po, (size_t)rb * D + c0,     c0,     acc[mf][nf][2]);
                    epi_apply(po, (size_t)rb * D + c0 + 1, c0 + 1, acc[mf][nf][3]);
                }
            }
        }
    }
}

// ---------------- small kernels ----------------
__global__ void combine_bias_kernel(
    const float* bzm, const float* bzs, const float* bias_z,
    const float* brm, const float* brs, const float* bias_r,
    const float* bhm, const float* bhs, const float* bias_h, float* cb) {
    int i = threadIdx.x;
    cb[i]         = bzm[i] + bzs[i] + bias_z[i];
    cb[D + i]     = brm[i] + brs[i] + bias_r[i];
    cb[2 * D + i] = bhm[i] + bhs[i] + bias_h[i];
}

__global__ void copy_kernel(const float* __restrict__ src, float* __restrict__ dst, int n4) {
    int i = blockIdx.x * blockDim.x + threadIdx.x;
    if (i < n4) ((float4*)dst)[i] = ((const float4*)src)[i];
}

// ---------------- edge scatter: m[dst] += t[src] * ew   (edge_index is int32) ----------------
__global__ void scatter_kernel(const int* __restrict__ ei, const float* __restrict__ ew,
                               const float* __restrict__ t, float* __restrict__ m, int E) {
    long long idx = (long long)blockIdx.x * blockDim.x + threadIdx.x;
    int e = (int)(idx >> 5);
    if (e >= E) return;
    int lane = (int)(idx & 31);
    int s = ei[e];
    int d = ei[(size_t)E + e];
    float w = ew[e];
    float4 v = *(const float4*)(t + (size_t)s * D + lane * 4);
    float4 r;
    r.x = v.x * w; r.y = v.y * w; r.z = v.z * w; r.w = v.w * w;
    float* p = m + (size_t)d * D + lane * 4;
    asm volatile("red.global.add.v4.f32 [%0], {%1,%2,%3,%4};"
                 :: "l"(p), "f"(r.x), "f"(r.y), "f"(r.z), "f"(r.w) : "memory");
}

// ---------------- head: attention gate + scale ----------------
__global__ void att_kernel(const float* __restrict__ h, const float* __restrict__ Wag,
                           const float* __restrict__ bag, float* __restrict__ out, int N) {
    long long idx = (long long)blockIdx.x * blockDim.x + threadIdx.x;
    int node = (int)(idx >> 5);
    if (node >= N) return;
    int lane = (int)(idx & 31);
    float4 hv = *(const float4*)(h + (size_t)node * D + lane * 4);
    float4 wv = *(const float4*)(Wag + lane * 4);
    float s = hv.x * wv.x + hv.y * wv.y + hv.z * wv.z + hv.w * wv.w;
#pragma unroll
    for (int o = 16; o > 0; o >>= 1) s += __shfl_xor_sync(0xFFFFFFFF, s, o);
    float att = sigf(s + bag[0]);
    float4 r;
    r.x = hv.x * att; r.y = hv.y * att; r.z = hv.z * att; r.w = hv.w * att;
    *(float4*)(out + (size_t)node * D + lane * 4) = r;
}

// ---------------- pooling (batch is int32) ----------------
__global__ void zero_pool_kernel(float* pmax, float* psum, float* cnt) {
    int i = blockIdx.x * blockDim.x + threadIdx.x;
    if (i < NGRAPH * D) { pmax[i] = 0.f; psum[i] = 0.f; }
    if (i < NGRAPH) cnt[i] = 0.f;
}

__global__ void pool_kernel(const float* __restrict__ h2, const int* __restrict__ batch,
                            float* __restrict__ pmax, float* __restrict__ psum,
                            float* __restrict__ cnt, int N) {
    long long idx = (long long)blockIdx.x * blockDim.x + threadIdx.x;
    int node = (int)(idx >> 5);
    if (node >= N) return;
    int lane = (int)(idx & 31);
    int g = batch[node];
    float4 v = *(const float4*)(h2 + (size_t)node * D + lane * 4);
    int* pm = (int*)(pmax + (size_t)g * D + lane * 4);
    atomicMax(pm + 0, __float_as_int(v.x));   // h2 >= 0 so int order == float order
    atomicMax(pm + 1, __float_as_int(v.y));
    atomicMax(pm + 2, __float_as_int(v.z));
    atomicMax(pm + 3, __float_as_int(v.w));
    float* ps = psum + (size_t)g * D + lane * 4;
    asm volatile("red.global.add.v4.f32 [%0], {%1,%2,%3,%4};"
                 :: "l"(ps), "f"(v.x), "f"(v.y), "f"(v.z), "f"(v.w) : "memory");
    if (lane == 0) atomicAdd(cnt + g, 1.0f);
}

// ---------------- final MLP ----------------
__global__ void mlp_kernel(const float* __restrict__ pmax, const float* __restrict__ psum,
                           const float* __restrict__ cnt,
                           const float* __restrict__ W1, const float* __restrict__ b1,
                           const float* __restrict__ W2, const float* __restrict__ b2,
                           float* __restrict__ out) {
    __shared__ float xp[2 * D];
    __shared__ float hid[D];
    int g = blockIdx.x;
    int t = threadIdx.x;  // 128 threads
    float c = fmaxf(cnt[g], 1.0f);
    xp[t]     = fmaxf(pmax[(size_t)g * D + t], 0.0f);
    xp[D + t] = psum[(size_t)g * D + t] / c;
    __syncthreads();
    float acc = b1[t];
#pragma unroll 8
    for (int j = 0; j < 2 * D; j++) acc += xp[j] * W1[(size_t)j * D + t];
    hid[t] = fmaxf(acc, 0.f);
    __syncthreads();
    if (t < NCLASS) {
        float o = b2[t];
#pragma unroll 8
        for (int k = 0; k < D; k++) o += hid[k] * W2[(size_t)k * NCLASS + t];
        out[(size_t)g * NCLASS + t] = o;
    }
}

// ---------------- host orchestration ----------------
extern "C" void kernel_launch(void* const* d_in, const int* in_sizes, int n_in,
                              void* d_out, int out_size) {
    const float* x     = (const float*)d_in[0];
    const int*   ei    = (const int*)d_in[1];    // int32 (jax x64 disabled)
    const int*   batch = (const int*)d_in[2];    // int32
    const float* ew    = (const float*)d_in[3];
    const float* Wa    = (const float*)d_in[4];
    const float *Wzm = (const float*)d_in[5],  *bzm = (const float*)d_in[6];
    const float *Wzs = (const float*)d_in[7],  *bzs = (const float*)d_in[8];
    const float *Wrm = (const float*)d_in[9],  *brm = (const float*)d_in[10];
    const float *Wrs = (const float*)d_in[11], *brs = (const float*)d_in[12];
    const float *Whm = (const float*)d_in[13], *bhm = (const float*)d_in[14];
    const float *Whs = (const float*)d_in[15], *bhs = (const float*)d_in[16];
    const float *Whg = (const float*)d_in[17], *bhg = (const float*)d_in[18];
    const float *Whl = (const float*)d_in[19], *bhl = (const float*)d_in[20];
    const float *bias_z = (const float*)d_in[21];
    const float *bias_r = (const float*)d_in[22];
    const float *bias_h = (const float*)d_in[23];
    const float *Wag = (const float*)d_in[24], *bag = (const float*)d_in[25];
    const float *Wae = (const float*)d_in[26], *bae = (const float*)d_in[27];
    const float *W1  = (const float*)d_in[28], *b1  = (const float*)d_in[29];
    const float *W2  = (const float*)d_in[30], *b2  = (const float*)d_in[31];
    float* out = (float*)d_out;

    const int N = in_sizes[0] / D;
    const int E = in_sizes[3];

    float *h, *t, *m, *z, *r, *ci, *gg, *cb, *pmax, *psum, *cnt;
    cudaGetSymbolAddress((void**)&h,  g_h);
    cudaGetSymbolAddress((void**)&t,  g_t);
    cudaGetSymbolAddress((void**)&m,  g_m);
    cudaGetSymbolAddress((void**)&z,  g_z);
    cudaGetSymbolAddress((void**)&r,  g_r);
    cudaGetSymbolAddress((void**)&ci, g_ci);
    cudaGetSymbolAddress((void**)&gg, g_g);
    cudaGetSymbolAddress((void**)&cb, g_cb);
    cudaGetSymbolAddress((void**)&pmax, g_pmax);
    cudaGetSymbolAddress((void**)&psum, g_psum);
    cudaGetSymbolAddress((void**)&cnt,  g_cnt);

    cudaFuncSetAttribute(gemm_fused<1>, cudaFuncAttributeMaxDynamicSharedMemorySize, GEMM_SMEM_BYTES);
    cudaFuncSetAttribute(gemm_fused<2>, cudaFuncAttributeMaxDynamicSharedMemorySize, GEMM_SMEM_BYTES);
    cudaFuncSetAttribute(gemm_fused<3>, cudaFuncAttributeMaxDynamicSharedMemorySize, GEMM_SMEM_BYTES);

    const float* cbz = cb;
    const float* cbr = cb + D;
    const float* cbh = cb + 2 * D;

    const int ND = N * D;
    const int n4 = ND / 4;
    const dim3 gg128((N + 127) / 128);

    combine_bias_kernel<<<1, D>>>(bzm, bzs, bias_z, brm, brs, bias_r, bhm, bhs, bias_h, cb);
    copy_kernel<<<(n4 + 255) / 256, 256>>>(x, h, n4);

    for (int layer = 0; layer < 3; layer++) {
        // K1 (A=h): t = h@Wa (also -> m for self-loops) ; zp = h@Wzs + cbz ; rp = h@Wrs + cbr
        {
            GemmParams p{};
            p.o[0] = { Wa,  nullptr, nullptr, m,       t, 6 };
            p.o[1] = { Wzs, cbz,     nullptr, nullptr, z, 0 };
            p.o[2] = { Wrs, cbr,     nullptr, nullptr, r, 0 };
            gemm_fused<3><<<gg128, 256, GEMM_SMEM_BYTES>>>(h, p, N);
        }
        // m[dst] += t[src]*ew
        {
            long long work = (long long)E * 32;
            scatter_kernel<<<(unsigned)((work + 255) / 256), 256>>>(ei, ew, t, m, E);
        }
        // K2 (A=m): z = sig(m@Wzm + zp) ; rh = sig(m@Wrm + rp)*h ; ci = m@Whm + cbh
        {
            GemmParams p{};
            p.o[0] = { Wzm, nullptr, z, nullptr, z,  1 };
            p.o[1] = { Wrm, nullptr, r, h,       r,  2 };
            p.o[2] = { Whm, cbh,     nullptr, nullptr, ci, 0 };
            gemm_fused<3><<<gg128, 256, GEMM_SMEM_BYTES>>>(m, p, N);
        }
        // K3 (A=rh): ci += rh@Whs
        {
            GemmParams p{};
            p.o[0] = { Whs, nullptr, nullptr, nullptr, ci, 3 };
            gemm_fused<1><<<gg128, 256, GEMM_SMEM_BYTES>>>(r, p, N);
        }
        // K4 (A=ci): g1 = ci@Whl + bhl ; h = z*(g1*sig(ci@Whg + bhg)) + (1-z)*h
        {
            GemmParams p{};
            p.o[0] = { Whl, bhl, nullptr, nullptr, gg, 0 };
            p.o[1] = { Whg, bhg, gg,      z,       h,  4 };
            gemm_fused<2><<<gg128, 256, GEMM_SMEM_BYTES>>>(ci, p, N);
        }
    }

    // attention gate: t = h * sigmoid(h @ Wag + bag)
    {
        long long work = (long long)N * 32;
        att_kernel<<<(unsigned)((work + 255) / 256), 256>>>(h, Wag, bag, t, N);
    }
    // m = relu(t @ Wae + bae)
    {
        GemmParams p{};
        p.o[0] = { Wae, bae, nullptr, nullptr, m, 5 };
        gemm_fused<1><<<gg128, 256, GEMM_SMEM_BYTES>>>(t, p, N);
    }

    // pooling + MLP head
    zero_pool_kernel<<<(NGRAPH * D + 255) / 256, 256>>>(pmax, psum, cnt);
    {
        long long work = (long long)N * 32;
        pool_kernel<<<(unsigned)((work + 255) / 256), 256>>>(m, batch, pmax, psum, cnt, N);
    }
    mlp_kernel<<<NGRAPH, D>>>(pmax, psum, cnt, W1, b1, W2, b2, out);
}

// round 9
// speedup vs baseline: 1.0302x; 1.0302x over previous
#include <cuda_runtime.h>
#include <cstdint>

#define D 128
#define NN_MAX 50000
#define NGRAPH 64
#define NCLASS 16

// ---------------- device scratch (allocation-free) ----------------
__device__ __align__(256) float g_h [NN_MAX * D];
__device__ __align__(256) float g_t [NN_MAX * D];
__device__ __align__(256) float g_m [NN_MAX * D];
__device__ __align__(256) float g_z [NN_MAX * D];
__device__ __align__(256) float g_r [NN_MAX * D];
__device__ __align__(256) float g_ci[NN_MAX * D];
__device__ __align__(256) float g_g [NN_MAX * D];
__device__ __align__(256) float g_cb[3 * D];     // combined biases: z, r, h
__device__ __align__(256) float g_pmax[NGRAPH * D];
__device__ __align__(256) float g_psum[NGRAPH * D];
__device__ __align__(256) float g_cnt [NGRAPH];

__device__ __forceinline__ float sigf(float x) { return 1.0f / (1.0f + __expf(-x)); }

__device__ __forceinline__ uint32_t to_tf32(float f) {
    uint32_t u;
    asm("cvt.rna.tf32.f32 %0, %1;" : "=r"(u) : "f"(f));
    return u;
}

// ---------------- fused multi-output TF32 tensor-core GEMM ----------------
// A staged ONCE (full K, stride 132) per block; W chunks double-buffered via register-prefetch.
// modes: 0: out = acc (+bias)   1: out = sigmoid(acc + aux1[idx])
//        2: r = sigmoid(acc+aux1[idx]); out = r*aux2[idx]
//        3: out[idx] += acc     4: g2 = acc+bias[col]; out = aux2*(aux1*sigf(g2)) + (1-aux2)*out
//        5: out = relu(acc + bias)   6: out = acc (+bias), also write to aux2 (second dest)
struct GemmOut {
    const float* W;
    const float* bias;
    const float* aux1;
    const float* aux2;
    float* out;
    int mode;
};
struct GemmParams { GemmOut o[3]; };

__device__ __forceinline__ void epi_apply(const GemmOut& o, size_t idx, int col, float v) {
    switch (o.mode) {
    case 0: if (o.bias) v += o.bias[col]; o.out[idx] = v; break;
    case 1: o.out[idx] = sigf(v + o.aux1[idx]); break;
    case 2: { float r = sigf(v + o.aux1[idx]); o.out[idx] = r * o.aux2[idx]; } break;
    case 3: o.out[idx] += v; break;
    case 4: { float g2 = v + o.bias[col]; float g1 = o.aux1[idx]; float zz = o.aux2[idx];
              o.out[idx] = zz * (g1 * sigf(g2)) + (1.f - zz) * o.out[idx]; } break;
    case 5: v += o.bias[col]; o.out[idx] = fmaxf(v, 0.f); break;
    case 6: if (o.bias) v += o.bias[col]; o.out[idx] = v; ((float*)o.aux2)[idx] = v; break;
    }
}

#define MMA_TF32(c, a, b) \
    asm volatile("mma.sync.aligned.m16n8k8.row.col.f32.tf32.tf32.f32 " \
        "{%0,%1,%2,%3}, {%4,%5,%6,%7}, {%8,%9}, {%0,%1,%2,%3};" \
        : "+f"((c)[0]), "+f"((c)[1]), "+f"((c)[2]), "+f"((c)[3]) \
        : "r"((a)[0]), "r"((a)[1]), "r"((a)[2]), "r"((a)[3]), "r"((b)[0]), "r"((b)[1]))

#define AS_STRIDE 132                         // full K (128) + pad 4 (132%32=4 -> conflict-free frags)
#define BS_STRIDE 132
#define AS_WORDS (128 * AS_STRIDE)
#define WS_WORDS (32 * BS_STRIDE)
#define GEMM_SMEM_BYTES ((AS_WORDS + 2 * WS_WORDS) * 4)   // 101,376 bytes

template<int NOUT>
__global__ void __launch_bounds__(256) gemm_fused(const float* __restrict__ A, GemmParams p, int N)
{
    extern __shared__ uint32_t smem[];
    uint32_t (*As)[AS_STRIDE]  = (uint32_t (*)[AS_STRIDE])smem;                    // [128][132]
    uint32_t (*Ws0)[BS_STRIDE] = (uint32_t (*)[BS_STRIDE])(smem + AS_WORDS);       // [32][132]
    uint32_t (*Ws1)[BS_STRIDE] = (uint32_t (*)[BS_STRIDE])(smem + AS_WORDS + WS_WORDS);

    const int tid  = threadIdx.x;
    const int lane = tid & 31;
    const int wid  = tid >> 5;
    const int wm   = wid >> 2;          // 0..1 -> m offset wm*64
    const int wn   = wid & 3;           // 0..3 -> n offset wn*32
    const int row0 = blockIdx.x * 128;
    const int gid  = lane >> 2;         // groupID 0..7
    const int tig  = lane & 3;          // thread-in-group 0..3

    // staging coords
    const int ar = tid >> 3, akg = (tid & 7) * 4;    // A: row ar+i*32, col kc*32+akg
    const int bk = tid >> 5, bng = (tid & 31) * 4;   // W: k bk+i*8, col bng

    // ---- stage full A once ----
#pragma unroll
    for (int kc = 0; kc < 4; kc++) {
#pragma unroll
        for (int i = 0; i < 4; i++) {
            int r = ar + i * 32;
            int grow = row0 + r;
            float4 v = make_float4(0.f, 0.f, 0.f, 0.f);
            if (grow < N) v = *(const float4*)&A[(size_t)grow * D + kc * 32 + akg];
            int c = kc * 32 + akg;
            As[r][c + 0] = to_tf32(v.x); As[r][c + 1] = to_tf32(v.y);
            As[r][c + 2] = to_tf32(v.z); As[r][c + 3] = to_tf32(v.w);
        }
    }

    for (int o = 0; o < NOUT; o++) {
        const float* __restrict__ W = p.o[o].W;
        float acc[4][4][4];
#pragma unroll
        for (int mf = 0; mf < 4; mf++)
#pragma unroll
            for (int nf = 0; nf < 4; nf++)
#pragma unroll
                for (int q = 0; q < 4; q++) acc[mf][nf][q] = 0.f;

        // preload W chunk 0 into registers
        float4 wreg[4];
#pragma unroll
        for (int i = 0; i < 4; i++)
            wreg[i] = *(const float4*)&W[(size_t)(bk + i * 8) * D + bng];

#pragma unroll
        for (int kcs = 0; kcs < 4; kcs++) {
            uint32_t (*Wsb)[BS_STRIDE] = (kcs & 1) ? Ws1 : Ws0;
            // commit prefetched regs into smem buffer
#pragma unroll
            for (int i = 0; i < 4; i++) {
                int k = bk + i * 8;
                Wsb[k][bng + 0] = to_tf32(wreg[i].x);
                Wsb[k][bng + 1] = to_tf32(wreg[i].y);
                Wsb[k][bng + 2] = to_tf32(wreg[i].z);
                Wsb[k][bng + 3] = to_tf32(wreg[i].w);
            }
            __syncthreads();
            // issue LDG for next chunk (latency hidden by compute below)
            if (kcs + 1 < 4) {
                const int kc = (kcs + 1) * 32;
#pragma unroll
                for (int i = 0; i < 4; i++)
                    wreg[i] = *(const float4*)&W[(size_t)(kc + bk + i * 8) * D + bng];
            }
            // compute on this chunk
            const int kofs = kcs * 32;
#pragma unroll
            for (int k8 = 0; k8 < 4; k8++) {
                const int kb = k8 * 8;
                uint32_t af[4][4];
#pragma unroll
                for (int mf = 0; mf < 4; mf++) {
                    int r = wm * 64 + mf * 16 + gid;
                    af[mf][0] = As[r][kofs + kb + tig];
                    af[mf][1] = As[r + 8][kofs + kb + tig];
                    af[mf][2] = As[r][kofs + kb + tig + 4];
                    af[mf][3] = As[r + 8][kofs + kb + tig + 4];
                }
                uint32_t bf[4][2];
#pragma unroll
                for (int nf = 0; nf < 4; nf++) {
                    int n = wn * 32 + nf * 8 + gid;
                    bf[nf][0] = Wsb[kb + tig][n];
                    bf[nf][1] = Wsb[kb + tig + 4][n];
                }
#pragma unroll
                for (int mf = 0; mf < 4; mf++)
#pragma unroll
                    for (int nf = 0; nf < 4; nf++)
                        MMA_TF32(acc[mf][nf], af[mf], bf[nf]);
            }
            __syncthreads();
        }

        // epilogue
        const GemmOut& po = p.o[o];
#pragma unroll
        for (int mf = 0; mf < 4; mf++) {
            int ra = row0 + wm * 64 + mf * 16 + gid;
            int rb = ra + 8;
#pragma unroll
            for (int nf = 0; nf < 4; nf++) {
                int c0 = wn * 32 + nf * 8 + tig * 2;
                if (ra < N) {
                    epi_apply(po, (size_t)ra * D + c0,     c0,     acc[mf][nf][0]);
                    epi_apply(po, (size_t)ra * D + c0 + 1, c0 + 1, acc[mf][nf][1]);
                }
                if (rb < N) {
                    epi_apply(po, (size_t)rb * D + c0,     c0,     acc[mf][nf][2]);
                    epi_apply(po, (size_t)rb * D + c0 + 1, c0 + 1, acc[mf][nf][3]);
                }
            }
        }
    }
}

// ---------------- small kernels ----------------
__global__ void combine_bias_kernel(
    const float* bzm, const float* bzs, const float* bias_z,
    const float* brm, const float* brs, const float* bias_r,
    const float* bhm, const float* bhs, const float* bias_h, float* cb) {
    int i = threadIdx.x;
    cb[i]         = bzm[i] + bzs[i] + bias_z[i];
    cb[D + i]     = brm[i] + brs[i] + bias_r[i];
    cb[2 * D + i] = bhm[i] + bhs[i] + bias_h[i];
}

__global__ void copy_kernel(const float* __restrict__ src, float* __restrict__ dst, int n4) {
    int i = blockIdx.x * blockDim.x + threadIdx.x;
    if (i < n4) ((float4*)dst)[i] = ((const float4*)src)[i];
}

// ---------------- edge scatter: m[dst] += t[src] * ew   (edge_index is int32) ----------------
__global__ void scatter_kernel(const int* __restrict__ ei, const float* __restrict__ ew,
                               const float* __restrict__ t, float* __restrict__ m, int E) {
    long long idx = (long long)blockIdx.x * blockDim.x + threadIdx.x;
    int e = (int)(idx >> 5);
    if (e >= E) return;
    int lane = (int)(idx & 31);
    int s = ei[e];
    int d = ei[(size_t)E + e];
    float w = ew[e];
    float4 v = *(const float4*)(t + (size_t)s * D + lane * 4);
    float4 r;
    r.x = v.x * w; r.y = v.y * w; r.z = v.z * w; r.w = v.w * w;
    float* p = m + (size_t)d * D + lane * 4;
    asm volatile("red.global.add.v4.f32 [%0], {%1,%2,%3,%4};"
                 :: "l"(p), "f"(r.x), "f"(r.y), "f"(r.z), "f"(r.w) : "memory");
}

// ---------------- head: attention gate + scale ----------------
__global__ void att_kernel(const float* __restrict__ h, const float* __restrict__ Wag,
                           const float* __restrict__ bag, float* __restrict__ out, int N) {
    long long idx = (long long)blockIdx.x * blockDim.x + threadIdx.x;
    int node = (int)(idx >> 5);
    if (node >= N) return;
    int lane = (int)(idx & 31);
    float4 hv = *(const float4*)(h + (size_t)node * D + lane * 4);
    float4 wv = *(const float4*)(Wag + lane * 4);
    float s = hv.x * wv.x + hv.y * wv.y + hv.z * wv.z + hv.w * wv.w;
#pragma unroll
    for (int o = 16; o > 0; o >>= 1) s += __shfl_xor_sync(0xFFFFFFFF, s, o);
    float att = sigf(s + bag[0]);
    float4 r;
    r.x = hv.x * att; r.y = hv.y * att; r.z = hv.z * att; r.w = hv.w * att;
    *(float4*)(out + (size_t)node * D + lane * 4) = r;
}

// ---------------- pooling (batch is int32) ----------------
__global__ void zero_pool_kernel(float* pmax, float* psum, float* cnt) {
    int i = blockIdx.x * blockDim.x + threadIdx.x;
    if (i < NGRAPH * D) { pmax[i] = 0.f; psum[i] = 0.f; }
    if (i < NGRAPH) cnt[i] = 0.f;
}

__global__ void pool_kernel(const float* __restrict__ h2, const int* __restrict__ batch,
                            float* __restrict__ pmax, float* __restrict__ psum,
                            float* __restrict__ cnt, int N) {
    long long idx = (long long)blockIdx.x * blockDim.x + threadIdx.x;
    int node = (int)(idx >> 5);
    if (node >= N) return;
    int lane = (int)(idx & 31);
    int g = batch[node];
    float4 v = *(const float4*)(h2 + (size_t)node * D + lane * 4);
    int* pm = (int*)(pmax + (size_t)g * D + lane * 4);
    atomicMax(pm + 0, __float_as_int(v.x));   // h2 >= 0 so int order == float order
    atomicMax(pm + 1, __float_as_int(v.y));
    atomicMax(pm + 2, __float_as_int(v.z));
    atomicMax(pm + 3, __float_as_int(v.w));
    float* ps = psum + (size_t)g * D + lane * 4;
    asm volatile("red.global.add.v4.f32 [%0], {%1,%2,%3,%4};"
                 :: "l"(ps), "f"(v.x), "f"(v.y), "f"(v.z), "f"(v.w) : "memory");
    if (lane == 0) atomicAdd(cnt + g, 1.0f);
}

// ---------------- final MLP ----------------
__global__ void mlp_kernel(const float* __restrict__ pmax, const float* __restrict__ psum,
                           const float* __restrict__ cnt,
                           const float* __restrict__ W1, const float* __restrict__ b1,
                           const float* __restrict__ W2, const float* __restrict__ b2,
                           float* __restrict__ out) {
    __shared__ float xp[2 * D];
    __shared__ float hid[D];
    int g = blockIdx.x;
    int t = threadIdx.x;  // 128 threads
    float c = fmaxf(cnt[g], 1.0f);
    xp[t]     = fmaxf(pmax[(size_t)g * D + t], 0.0f);
    xp[D + t] = psum[(size_t)g * D + t] / c;
    __syncthreads();
    float acc = b1[t];
#pragma unroll 8
    for (int j = 0; j < 2 * D; j++) acc += xp[j] * W1[(size_t)j * D + t];
    hid[t] = fmaxf(acc, 0.f);
    __syncthreads();
    if (t < NCLASS) {
        float o = b2[t];
#pragma unroll 8
        for (int k = 0; k < D; k++) o += hid[k] * W2[(size_t)k * NCLASS + t];
        out[(size_t)g * NCLASS + t] = o;
    }
}

// ---------------- host orchestration ----------------
extern "C" void kernel_launch(void* const* d_in, const int* in_sizes, int n_in,
                              void* d_out, int out_size) {
    const float* x     = (const float*)d_in[0];
    const int*   ei    = (const int*)d_in[1];    // int32 (jax x64 disabled)
    const int*   batch = (const int*)d_in[2];    // int32
    const float* ew    = (const float*)d_in[3];
    const float* Wa    = (const float*)d_in[4];
    const float *Wzm = (const float*)d_in[5],  *bzm = (const float*)d_in[6];
    const float *Wzs = (const float*)d_in[7],  *bzs = (const float*)d_in[8];
    const float *Wrm = (const float*)d_in[9],  *brm = (const float*)d_in[10];
    const float *Wrs = (const float*)d_in[11], *brs = (const float*)d_in[12];
    const float *Whm = (const float*)d_in[13], *bhm = (const float*)d_in[14];
    const float *Whs = (const float*)d_in[15], *bhs = (const float*)d_in[16];
    const float *Whg = (const float*)d_in[17], *bhg = (const float*)d_in[18];
    const float *Whl = (const float*)d_in[19], *bhl = (const float*)d_in[20];
    const float *bias_z = (const float*)d_in[21];
    const float *bias_r = (const float*)d_in[22];
    const float *bias_h = (const float*)d_in[23];
    const float *Wag = (const float*)d_in[24], *bag = (const float*)d_in[25];
    const float *Wae = (const float*)d_in[26], *bae = (const float*)d_in[27];
    const float *W1  = (const float*)d_in[28], *b1  = (const float*)d_in[29];
    const float *W2  = (const float*)d_in[30], *b2  = (const float*)d_in[31];
    float* out = (float*)d_out;

    const int N = in_sizes[0] / D;
    const int E = in_sizes[3];

    float *h, *t, *m, *z, *r, *ci, *gg, *cb, *pmax, *psum, *cnt;
    cudaGetSymbolAddress((void**)&h,  g_h);
    cudaGetSymbolAddress((void**)&t,  g_t);
    cudaGetSymbolAddress((void**)&m,  g_m);
    cudaGetSymbolAddress((void**)&z,  g_z);
    cudaGetSymbolAddress((void**)&r,  g_r);
    cudaGetSymbolAddress((void**)&ci, g_ci);
    cudaGetSymbolAddress((void**)&gg, g_g);
    cudaGetSymbolAddress((void**)&cb, g_cb);
    cudaGetSymbolAddress((void**)&pmax, g_pmax);
    cudaGetSymbolAddress((void**)&psum, g_psum);
    cudaGetSymbolAddress((void**)&cnt,  g_cnt);

    cudaFuncSetAttribute(gemm_fused<1>, cudaFuncAttributeMaxDynamicSharedMemorySize, GEMM_SMEM_BYTES);
    cudaFuncSetAttribute(gemm_fused<2>, cudaFuncAttributeMaxDynamicSharedMemorySize, GEMM_SMEM_BYTES);
    cudaFuncSetAttribute(gemm_fused<3>, cudaFuncAttributeMaxDynamicSharedMemorySize, GEMM_SMEM_BYTES);

    const float* cbz = cb;
    const float* cbr = cb + D;
    const float* cbh = cb + 2 * D;

    const int ND = N * D;
    const int n4 = ND / 4;
    const dim3 gg128((N + 127) / 128);

    combine_bias_kernel<<<1, D>>>(bzm, bzs, bias_z, brm, brs, bias_r, bhm, bhs, bias_h, cb);
    copy_kernel<<<(n4 + 255) / 256, 256>>>(x, h, n4);

    for (int layer = 0; layer < 3; layer++) {
        // K1 (A=h): t = h@Wa (also -> m for self-loops) ; zp = h@Wzs + cbz ; rp = h@Wrs + cbr
        {
            GemmParams p{};
            p.o[0] = { Wa,  nullptr, nullptr, m,       t, 6 };
            p.o[1] = { Wzs, cbz,     nullptr, nullptr, z, 0 };
            p.o[2] = { Wrs, cbr,     nullptr, nullptr, r, 0 };
            gemm_fused<3><<<gg128, 256, GEMM_SMEM_BYTES>>>(h, p, N);
        }
        // m[dst] += t[src]*ew
        {
            long long work = (long long)E * 32;
            scatter_kernel<<<(unsigned)((work + 255) / 256), 256>>>(ei, ew, t, m, E);
        }
        // K2 (A=m): z = sig(m@Wzm + zp) ; rh = sig(m@Wrm + rp)*h ; ci = m@Whm + cbh
        {
            GemmParams p{};
            p.o[0] = { Wzm, nullptr, z, nullptr, z,  1 };
            p.o[1] = { Wrm, nullptr, r, h,       r,  2 };
            p.o[2] = { Whm, cbh,     nullptr, nullptr, ci, 0 };
            gemm_fused<3><<<gg128, 256, GEMM_SMEM_BYTES>>>(m, p, N);
        }
        // K3 (A=rh): ci += rh@Whs
        {
            GemmParams p{};
            p.o[0] = { Whs, nullptr, nullptr, nullptr, ci, 3 };
            gemm_fused<1><<<gg128, 256, GEMM_SMEM_BYTES>>>(r, p, N);
        }
        // K4 (A=ci): g1 = ci@Whl + bhl ; h = z*(g1*sig(ci@Whg + bhg)) + (1-z)*h
        {
            GemmParams p{};
            p.o[0] = { Whl, bhl, nullptr, nullptr, gg, 0 };
            p.o[1] = { Whg, bhg, gg,      z,       h,  4 };
            gemm_fused<2><<<gg128, 256, GEMM_SMEM_BYTES>>>(ci, p, N);
        }
    }

    // attention gate: t = h * sigmoid(h @ Wag + bag)
    {
        long long work = (long long)N * 32;
        att_kernel<<<(unsigned)((work + 255) / 256), 256>>>(h, Wag, bag, t, N);
    }
    // m = relu(t @ Wae + bae)
    {
        GemmParams p{};
        p.o[0] = { Wae, bae, nullptr, nullptr, m, 5 };
        gemm_fused<1><<<gg128, 256, GEMM_SMEM_BYTES>>>(t, p, N);
    }

    // pooling + MLP head
    zero_pool_kernel<<<(NGRAPH * D + 255) / 256, 256>>>(pmax, psum, cnt);
    {
        long long work = (long long)N * 32;
        pool_kernel<<<(unsigned)((work + 255) / 256), 256>>>(m, batch, pmax, psum, cnt, N);
    }
    mlp_kernel<<<NGRAPH, D>>>(pmax, psum, cnt, W1, b1, W2, b2, out);
}

// round 10
// speedup vs baseline: 1.2225x; 1.1866x over previous
#include <cuda_runtime.h>
#include <cstdint>

#define D 128
#define NN_MAX 50000
#define NGRAPH 64
#define NCLASS 16

// ---------------- device scratch (allocation-free) ----------------
__device__ __align__(256) float g_h [NN_MAX * D];
__device__ __align__(256) float g_t [NN_MAX * D];
__device__ __align__(256) float g_m [NN_MAX * D];
__device__ __align__(256) float g_z [NN_MAX * D];
__device__ __align__(256) float g_r [NN_MAX * D];
__device__ __align__(256) float g_ci[NN_MAX * D];
__device__ __align__(256) float g_g [NN_MAX * D];
__device__ __align__(256) float g_cb[3 * D];     // combined biases: z, r, h
__device__ __align__(256) float g_pmax[NGRAPH * D];
__device__ __align__(256) float g_psum[NGRAPH * D];
__device__ __align__(256) float g_cnt [NGRAPH];

__device__ __forceinline__ float sigf(float x) { return 1.0f / (1.0f + __expf(-x)); }

__device__ __forceinline__ uint32_t to_tf32(float f) {
    uint32_t u;
    asm("cvt.rna.tf32.f32 %0, %1;" : "=r"(u) : "f"(f));
    return u;
}

// ---------------- fused multi-output TF32 tensor-core GEMM (R5-proven core) ----------------
// modes: 0: out = acc (+bias)   1: out = sigmoid(acc + aux1[idx])
//        2: r = sigmoid(acc+aux1[idx]); out = r*aux2[idx]
//        3: out[idx] += acc     4: g2 = acc+bias[col]; out = aux2*(aux1*sigf(g2)) + (1-aux2)*out
//        5: out = relu(acc + bias)   6: out = acc (+bias), also write to aux2 (second dest)
struct GemmOut {
    const float* W;
    const float* bias;
    const float* aux1;
    const float* aux2;
    float* out;
    int mode;
};
struct GemmParams { GemmOut o[3]; };

__device__ __forceinline__ void epi_apply(const GemmOut& o, size_t idx, int col, float v) {
    switch (o.mode) {
    case 0: if (o.bias) v += o.bias[col]; o.out[idx] = v; break;
    case 1: o.out[idx] = sigf(v + o.aux1[idx]); break;
    case 2: { float r = sigf(v + o.aux1[idx]); o.out[idx] = r * o.aux2[idx]; } break;
    case 3: o.out[idx] += v; break;
    case 4: { float g2 = v + o.bias[col]; float g1 = o.aux1[idx]; float zz = o.aux2[idx];
              o.out[idx] = zz * (g1 * sigf(g2)) + (1.f - zz) * o.out[idx]; } break;
    case 5: v += o.bias[col]; o.out[idx] = fmaxf(v, 0.f); break;
    case 6: if (o.bias) v += o.bias[col]; o.out[idx] = v; ((float*)o.aux2)[idx] = v; break;
    }
}

#define MMA_TF32(c, a, b) \
    asm volatile("mma.sync.aligned.m16n8k8.row.col.f32.tf32.tf32.f32 " \
        "{%0,%1,%2,%3}, {%4,%5,%6,%7}, {%8,%9}, {%0,%1,%2,%3};" \
        : "+f"((c)[0]), "+f"((c)[1]), "+f"((c)[2]), "+f"((c)[3]) \
        : "r"((a)[0]), "r"((a)[1]), "r"((a)[2]), "r"((a)[3]), "r"((b)[0]), "r"((b)[1]))

template<int NOUT>
__global__ void __launch_bounds__(256, 2) gemm_fused(const float* __restrict__ A, GemmParams p, int N)
{
    __shared__ uint32_t As[128][36];   // [row][k-chunk], pad 4 -> conflict-free A-frag loads
    __shared__ uint32_t Bs[32][132];   // [k][n],  pad 4 -> coalesced stores, ~2-way frag loads

    const int tid  = threadIdx.x;
    const int lane = tid & 31;
    const int wid  = tid >> 5;
    const int wm   = wid >> 2;          // 0..1 -> m offset wm*64
    const int wn   = wid & 3;           // 0..3 -> n offset wn*32
    const int row0 = blockIdx.x * 128;
    const int gid  = lane >> 2;         // groupID 0..7
    const int tig  = lane & 3;          // thread-in-group 0..3

    for (int o = 0; o < NOUT; o++) {
        const float* __restrict__ W = p.o[o].W;
        float acc[4][4][4];             // [mfrag][nfrag][reg]
#pragma unroll
        for (int mf = 0; mf < 4; mf++)
#pragma unroll
            for (int nf = 0; nf < 4; nf++)
#pragma unroll
                for (int q = 0; q < 4; q++) acc[mf][nf][q] = 0.f;

        for (int kc = 0; kc < D; kc += 32) {
            // A chunk: 128 rows x 32 k  (1024 float4; 4 per thread)
#pragma unroll
            for (int i = 0; i < 4; i++) {
                int f = tid + i * 256;
                int r = f >> 3, kg = (f & 7) * 4;
                int grow = row0 + r;
                float4 v = make_float4(0.f, 0.f, 0.f, 0.f);
                if (grow < N) v = *(const float4*)&A[(size_t)grow * D + kc + kg];
                As[r][kg + 0] = to_tf32(v.x); As[r][kg + 1] = to_tf32(v.y);
                As[r][kg + 2] = to_tf32(v.z); As[r][kg + 3] = to_tf32(v.w);
            }
            // W chunk: 32 k-rows x 128 n  (1024 float4; 4 per thread), k-major as-is
#pragma unroll
            for (int i = 0; i < 4; i++) {
                int f = tid + i * 256;
                int k = f >> 5, ng = (f & 31) * 4;
                float4 v = *(const float4*)&W[(size_t)(kc + k) * D + ng];
                Bs[k][ng + 0] = to_tf32(v.x); Bs[k][ng + 1] = to_tf32(v.y);
                Bs[k][ng + 2] = to_tf32(v.z); Bs[k][ng + 3] = to_tf32(v.w);
            }
            __syncthreads();

#pragma unroll
            for (int k8 = 0; k8 < 4; k8++) {
                const int kb = k8 * 8;
                uint32_t af[4][4];
#pragma unroll
                for (int mf = 0; mf < 4; mf++) {
                    int r = wm * 64 + mf * 16 + gid;
                    af[mf][0] = As[r][kb + tig];
                    af[mf][1] = As[r + 8][kb + tig];
                    af[mf][2] = As[r][kb + tig + 4];
                    af[mf][3] = As[r + 8][kb + tig + 4];
                }
                uint32_t bf[4][2];
#pragma unroll
                for (int nf = 0; nf < 4; nf++) {
                    int n = wn * 32 + nf * 8 + gid;
                    bf[nf][0] = Bs[kb + tig][n];
                    bf[nf][1] = Bs[kb + tig + 4][n];
                }
#pragma unroll
                for (int mf = 0; mf < 4; mf++)
#pragma unroll
                    for (int nf = 0; nf < 4; nf++)
                        MMA_TF32(acc[mf][nf], af[mf], bf[nf]);
            }
            __syncthreads();
        }

        // epilogue
        const GemmOut& po = p.o[o];
#pragma unroll
        for (int mf = 0; mf < 4; mf++) {
            int ra = row0 + wm * 64 + mf * 16 + gid;
            int rb = ra + 8;
#pragma unroll
            for (int nf = 0; nf < 4; nf++) {
                int c0 = wn * 32 + nf * 8 + tig * 2;
                if (ra < N) {
                    epi_apply(po, (size_t)ra * D + c0,     c0,     acc[mf][nf][0]);
                    epi_apply(po, (size_t)ra * D + c0 + 1, c0 + 1, acc[mf][nf][1]);
                }
                if (rb < N) {
                    epi_apply(po, (size_t)rb * D + c0,     c0,     acc[mf][nf][2]);
                    epi_apply(po, (size_t)rb * D + c0 + 1, c0 + 1, acc[mf][nf][3]);
                }
            }
        }
        if (o + 1 < NOUT) __syncthreads();
    }
}

// ---------------- small kernels ----------------
__global__ void combine_bias_kernel(
    const float* bzm, const float* bzs, const float* bias_z,
    const float* brm, const float* brs, const float* bias_r,
    const float* bhm, const float* bhs, const float* bias_h, float* cb) {
    int i = threadIdx.x;
    cb[i]         = bzm[i] + bzs[i] + bias_z[i];
    cb[D + i]     = brm[i] + brs[i] + bias_r[i];
    cb[2 * D + i] = bhm[i] + bhs[i] + bias_h[i];
}

__global__ void copy_kernel(const float* __restrict__ src, float* __restrict__ dst, int n4) {
    int i = blockIdx.x * blockDim.x + threadIdx.x;
    if (i < n4) ((float4*)dst)[i] = ((const float4*)src)[i];
}

// ---------------- edge scatter: m[dst] += t[src] * ew   (edge_index is int32) ----------------
__global__ void scatter_kernel(const int* __restrict__ ei, const float* __restrict__ ew,
                               const float* __restrict__ t, float* __restrict__ m, int E) {
    long long idx = (long long)blockIdx.x * blockDim.x + threadIdx.x;
    int e = (int)(idx >> 5);
    if (e >= E) return;
    int lane = (int)(idx & 31);
    int s = ei[e];
    int d = ei[(size_t)E + e];
    float w = ew[e];
    float4 v = *(const float4*)(t + (size_t)s * D + lane * 4);
    float4 r;
    r.x = v.x * w; r.y = v.y * w; r.z = v.z * w; r.w = v.w * w;
    float* p = m + (size_t)d * D + lane * 4;
    asm volatile("red.global.add.v4.f32 [%0], {%1,%2,%3,%4};"
                 :: "l"(p), "f"(r.x), "f"(r.y), "f"(r.z), "f"(r.w) : "memory");
}

// ---------------- head: attention gate + scale ----------------
__global__ void att_kernel(const float* __restrict__ h, const float* __restrict__ Wag,
                           const float* __restrict__ bag, float* __restrict__ out, int N) {
    long long idx = (long long)blockIdx.x * blockDim.x + threadIdx.x;
    int node = (int)(idx >> 5);
    if (node >= N) return;
    int lane = (int)(idx & 31);
    float4 hv = *(const float4*)(h + (size_t)node * D + lane * 4);
    float4 wv = *(const float4*)(Wag + lane * 4);
    float s = hv.x * wv.x + hv.y * wv.y + hv.z * wv.z + hv.w * wv.w;
#pragma unroll
    for (int o = 16; o > 0; o >>= 1) s += __shfl_xor_sync(0xFFFFFFFF, s, o);
    float att = sigf(s + bag[0]);
    float4 r;
    r.x = hv.x * att; r.y = hv.y * att; r.z = hv.z * att; r.w = hv.w * att;
    *(float4*)(out + (size_t)node * D + lane * 4) = r;
}

// ---------------- pooling (batch is int32) ----------------
__global__ void zero_pool_kernel(float* pmax, float* psum, float* cnt) {
    int i = blockIdx.x * blockDim.x + threadIdx.x;
    if (i < NGRAPH * D) { pmax[i] = 0.f; psum[i] = 0.f; }
    if (i < NGRAPH) cnt[i] = 0.f;
}

__global__ void pool_kernel(const float* __restrict__ h2, const int* __restrict__ batch,
                            float* __restrict__ pmax, float* __restrict__ psum,
                            float* __restrict__ cnt, int N) {
    long long idx = (long long)blockIdx.x * blockDim.x + threadIdx.x;
    int node = (int)(idx >> 5);
    if (node >= N) return;
    int lane = (int)(idx & 31);
    int g = batch[node];
    float4 v = *(const float4*)(h2 + (size_t)node * D + lane * 4);
    int* pm = (int*)(pmax + (size_t)g * D + lane * 4);
    atomicMax(pm + 0, __float_as_int(v.x));   // h2 >= 0 so int order == float order
    atomicMax(pm + 1, __float_as_int(v.y));
    atomicMax(pm + 2, __float_as_int(v.z));
    atomicMax(pm + 3, __float_as_int(v.w));
    float* ps = psum + (size_t)g * D + lane * 4;
    asm volatile("red.global.add.v4.f32 [%0], {%1,%2,%3,%4};"
                 :: "l"(ps), "f"(v.x), "f"(v.y), "f"(v.z), "f"(v.w) : "memory");
    if (lane == 0) atomicAdd(cnt + g, 1.0f);
}

// ---------------- final MLP ----------------
__global__ void mlp_kernel(const float* __restrict__ pmax, const float* __restrict__ psum,
                           const float* __restrict__ cnt,
                           const float* __restrict__ W1, const float* __restrict__ b1,
                           const float* __restrict__ W2, const float* __restrict__ b2,
                           float* __restrict__ out) {
    __shared__ float xp[2 * D];
    __shared__ float hid[D];
    int g = blockIdx.x;
    int t = threadIdx.x;  // 128 threads
    float c = fmaxf(cnt[g], 1.0f);
    xp[t]     = fmaxf(pmax[(size_t)g * D + t], 0.0f);
    xp[D + t] = psum[(size_t)g * D + t] / c;
    __syncthreads();
    float acc = b1[t];
#pragma unroll 8
    for (int j = 0; j < 2 * D; j++) acc += xp[j] * W1[(size_t)j * D + t];
    hid[t] = fmaxf(acc, 0.f);
    __syncthreads();
    if (t < NCLASS) {
        float o = b2[t];
#pragma unroll 8
        for (int k = 0; k < D; k++) o += hid[k] * W2[(size_t)k * NCLASS + t];
        out[(size_t)g * NCLASS + t] = o;
    }
}

// ---------------- host orchestration ----------------
extern "C" void kernel_launch(void* const* d_in, const int* in_sizes, int n_in,
                              void* d_out, int out_size) {
    const float* x     = (const float*)d_in[0];
    const int*   ei    = (const int*)d_in[1];    // int32 (jax x64 disabled)
    const int*   batch = (const int*)d_in[2];    // int32
    const float* ew    = (const float*)d_in[3];
    const float* Wa    = (const float*)d_in[4];
    const float *Wzm = (const float*)d_in[5],  *bzm = (const float*)d_in[6];
    const float *Wzs = (const float*)d_in[7],  *bzs = (const float*)d_in[8];
    const float *Wrm = (const float*)d_in[9],  *brm = (const float*)d_in[10];
    const float *Wrs = (const float*)d_in[11], *brs = (const float*)d_in[12];
    const float *Whm = (const float*)d_in[13], *bhm = (const float*)d_in[14];
    const float *Whs = (const float*)d_in[15], *bhs = (const float*)d_in[16];
    const float *Whg = (const float*)d_in[17], *bhg = (const float*)d_in[18];
    const float *Whl = (const float*)d_in[19], *bhl = (const float*)d_in[20];
    const float *bias_z = (const float*)d_in[21];
    const float *bias_r = (const float*)d_in[22];
    const float *bias_h = (const float*)d_in[23];
    const float *Wag = (const float*)d_in[24], *bag = (const float*)d_in[25];
    const float *Wae = (const float*)d_in[26], *bae = (const float*)d_in[27];
    const float *W1  = (const float*)d_in[28], *b1  = (const float*)d_in[29];
    const float *W2  = (const float*)d_in[30], *b2  = (const float*)d_in[31];
    float* out = (float*)d_out;

    const int N = in_sizes[0] / D;
    const int E = in_sizes[3];

    float *h, *t, *m, *z, *r, *ci, *gg, *cb, *pmax, *psum, *cnt;
    cudaGetSymbolAddress((void**)&h,  g_h);
    cudaGetSymbolAddress((void**)&t,  g_t);
    cudaGetSymbolAddress((void**)&m,  g_m);
    cudaGetSymbolAddress((void**)&z,  g_z);
    cudaGetSymbolAddress((void**)&r,  g_r);
    cudaGetSymbolAddress((void**)&ci, g_ci);
    cudaGetSymbolAddress((void**)&gg, g_g);
    cudaGetSymbolAddress((void**)&cb, g_cb);
    cudaGetSymbolAddress((void**)&pmax, g_pmax);
    cudaGetSymbolAddress((void**)&psum, g_psum);
    cudaGetSymbolAddress((void**)&cnt,  g_cnt);

    const float* cbz = cb;
    const float* cbr = cb + D;
    const float* cbh = cb + 2 * D;

    const int ND = N * D;
    const int n4 = ND / 4;
    const dim3 gg128((N + 127) / 128);

    combine_bias_kernel<<<1, D>>>(bzm, bzs, bias_z, brm, brs, bias_r, bhm, bhs, bias_h, cb);
    copy_kernel<<<(n4 + 255) / 256, 256>>>(x, h, n4);

    for (int layer = 0; layer < 3; layer++) {
        // K1 (A=h): t = h@Wa (also -> m for self-loops) ; zp = h@Wzs + cbz ; rp = h@Wrs + cbr
        {
            GemmParams p{};
            p.o[0] = { Wa,  nullptr, nullptr, m,       t, 6 };
            p.o[1] = { Wzs, cbz,     nullptr, nullptr, z, 0 };
            p.o[2] = { Wrs, cbr,     nullptr, nullptr, r, 0 };
            gemm_fused<3><<<gg128, 256>>>(h, p, N);
        }
        // m[dst] += t[src]*ew
        {
            long long work = (long long)E * 32;
            scatter_kernel<<<(unsigned)((work + 255) / 256), 256>>>(ei, ew, t, m, E);
        }
        // K2 (A=m): z = sig(m@Wzm + zp) ; rh = sig(m@Wrm + rp)*h ; ci = m@Whm + cbh
        {
            GemmParams p{};
            p.o[0] = { Wzm, nullptr, z, nullptr, z,  1 };
            p.o[1] = { Wrm, nullptr, r, h,       r,  2 };
            p.o[2] = { Whm, cbh,     nullptr, nullptr, ci, 0 };
            gemm_fused<3><<<gg128, 256>>>(m, p, N);
        }
        // K3 (A=rh): ci += rh@Whs
        {
            GemmParams p{};
            p.o[0] = { Whs, nullptr, nullptr, nullptr, ci, 3 };
            gemm_fused<1><<<gg128, 256>>>(r, p, N);
        }
        // K4 (A=ci): g1 = ci@Whl + bhl ; h = z*(g1*sig(ci@Whg + bhg)) + (1-z)*h
        {
            GemmParams p{};
            p.o[0] = { Whl, bhl, nullptr, nullptr, gg, 0 };
            p.o[1] = { Whg, bhg, gg,      z,       h,  4 };
            gemm_fused<2><<<gg128, 256>>>(ci, p, N);
        }
    }

    // attention gate: t = h * sigmoid(h @ Wag + bag)
    {
        long long work = (long long)N * 32;
        att_kernel<<<(unsigned)((work + 255) / 256), 256>>>(h, Wag, bag, t, N);
    }
    // m = relu(t @ Wae + bae)
    {
        GemmParams p{};
        p.o[0] = { Wae, bae, nullptr, nullptr, m, 5 };
        gemm_fused<1><<<gg128, 256>>>(t, p, N);
    }

    // pooling + MLP head
    zero_pool_kernel<<<(NGRAPH * D + 255) / 256, 256>>>(pmax, psum, cnt);
    {
        long long work = (long long)N * 32;
        pool_kernel<<<(unsigned)((work + 255) / 256), 256>>>(m, batch, pmax, psum, cnt, N);
    }
    mlp_kernel<<<NGRAPH, D>>>(pmax, psum, cnt, W1, b1, W2, b2, out);
}

// round 11
// speedup vs baseline: 1.2283x; 1.0047x over previous
#include <cuda_runtime.h>
#include <cstdint>

#define D 128
#define NN_MAX 50000
#define NGRAPH 64
#define NCLASS 16

// ---------------- device scratch (allocation-free) ----------------
__device__ __align__(256) float g_h [NN_MAX * D];
__device__ __align__(256) float g_t [NN_MAX * D];
__device__ __align__(256) float g_m [NN_MAX * D];
__device__ __align__(256) float g_z [NN_MAX * D];
__device__ __align__(256) float g_r [NN_MAX * D];
__device__ __align__(256) float g_ci[NN_MAX * D];
__device__ __align__(256) float g_g [NN_MAX * D];
__device__ __align__(256) float g_cb[3 * D];     // combined biases: z, r, h
__device__ __align__(256) float g_pmax[NGRAPH * D];
__device__ __align__(256) float g_psum[NGRAPH * D];
__device__ __align__(256) float g_cnt [NGRAPH];

__device__ __forceinline__ float sigf(float x) { return 1.0f / (1.0f + __expf(-x)); }

__device__ __forceinline__ uint32_t to_tf32(float f) {
    uint32_t u;
    asm("cvt.rna.tf32.f32 %0, %1;" : "=r"(u) : "f"(f));
    return u;
}

// ---------------- fused multi-output TF32 tensor-core GEMM (R5-proven core) ----------------
// modes: 0: out = acc (+bias)   1: out = sigmoid(acc + aux1[idx])
//        2: r = sigmoid(acc+aux1[idx]); out = r*aux2[idx]
//        3: out[idx] += acc     4: g2 = acc+bias[col]; out = aux2*(aux1*sigf(g2)) + (1-aux2)*out
//        5: out = relu(acc + bias)   6: out = acc (+bias), also write to aux2 (second dest)
struct GemmOut {
    const float* W;
    const float* bias;
    const float* aux1;
    const float* aux2;
    float* out;
    int mode;
};
struct GemmParams { GemmOut o[3]; };

__device__ __forceinline__ void epi_apply(const GemmOut& o, size_t idx, int col, float v) {
    switch (o.mode) {
    case 0: if (o.bias) v += o.bias[col]; o.out[idx] = v; break;
    case 1: o.out[idx] = sigf(v + o.aux1[idx]); break;
    case 2: { float r = sigf(v + o.aux1[idx]); o.out[idx] = r * o.aux2[idx]; } break;
    case 3: o.out[idx] += v; break;
    case 4: { float g2 = v + o.bias[col]; float g1 = o.aux1[idx]; float zz = o.aux2[idx];
              o.out[idx] = zz * (g1 * sigf(g2)) + (1.f - zz) * o.out[idx]; } break;
    case 5: v += o.bias[col]; o.out[idx] = fmaxf(v, 0.f); break;
    case 6: if (o.bias) v += o.bias[col]; o.out[idx] = v; ((float*)o.aux2)[idx] = v; break;
    }
}

#define MMA_TF32(c, a, b) \
    asm volatile("mma.sync.aligned.m16n8k8.row.col.f32.tf32.tf32.f32 " \
        "{%0,%1,%2,%3}, {%4,%5,%6,%7}, {%8,%9}, {%0,%1,%2,%3};" \
        : "+f"((c)[0]), "+f"((c)[1]), "+f"((c)[2]), "+f"((c)[3]) \
        : "r"((a)[0]), "r"((a)[1]), "r"((a)[2]), "r"((a)[3]), "r"((b)[0]), "r"((b)[1]))

template<int NOUT>
__global__ void __launch_bounds__(256) gemm_fused(const float* __restrict__ A, GemmParams p, int N)
{
    __shared__ uint32_t As[128][36];   // [row][k-chunk], pad 4 -> conflict-free A-frag loads
    __shared__ uint32_t Bs[32][132];   // [k][n],  pad 4 -> coalesced stores, ~2-way frag loads

    const int tid  = threadIdx.x;
    const int lane = tid & 31;
    const int wid  = tid >> 5;
    const int wm   = wid >> 2;          // 0..1 -> m offset wm*64
    const int wn   = wid & 3;           // 0..3 -> n offset wn*32
    const int row0 = blockIdx.x * 128;
    const int gid  = lane >> 2;         // groupID 0..7
    const int tig  = lane & 3;          // thread-in-group 0..3

    for (int o = 0; o < NOUT; o++) {
        const float* __restrict__ W = p.o[o].W;
        float acc[4][4][4];             // [mfrag][nfrag][reg]
#pragma unroll
        for (int mf = 0; mf < 4; mf++)
#pragma unroll
            for (int nf = 0; nf < 4; nf++)
#pragma unroll
                for (int q = 0; q < 4; q++) acc[mf][nf][q] = 0.f;

        for (int kc = 0; kc < D; kc += 32) {
            // A chunk: 128 rows x 32 k  (1024 float4; 4 per thread)
#pragma unroll
            for (int i = 0; i < 4; i++) {
                int f = tid + i * 256;
                int r = f >> 3, kg = (f & 7) * 4;
                int grow = row0 + r;
                float4 v = make_float4(0.f, 0.f, 0.f, 0.f);
                if (grow < N) v = *(const float4*)&A[(size_t)grow * D + kc + kg];
                As[r][kg + 0] = to_tf32(v.x); As[r][kg + 1] = to_tf32(v.y);
                As[r][kg + 2] = to_tf32(v.z); As[r][kg + 3] = to_tf32(v.w);
            }
            // W chunk: 32 k-rows x 128 n  (1024 float4; 4 per thread), k-major as-is
#pragma unroll
            for (int i = 0; i < 4; i++) {
                int f = tid + i * 256;
                int k = f >> 5, ng = (f & 31) * 4;
                float4 v = *(const float4*)&W[(size_t)(kc + k) * D + ng];
                Bs[k][ng + 0] = to_tf32(v.x); Bs[k][ng + 1] = to_tf32(v.y);
                Bs[k][ng + 2] = to_tf32(v.z); Bs[k][ng + 3] = to_tf32(v.w);
            }
            __syncthreads();

#pragma unroll
            for (int k8 = 0; k8 < 4; k8++) {
                const int kb = k8 * 8;
                uint32_t af[4][4];
#pragma unroll
                for (int mf = 0; mf < 4; mf++) {
                    int r = wm * 64 + mf * 16 + gid;
                    af[mf][0] = As[r][kb + tig];
                    af[mf][1] = As[r + 8][kb + tig];
                    af[mf][2] = As[r][kb + tig + 4];
                    af[mf][3] = As[r + 8][kb + tig + 4];
                }
                uint32_t bf[4][2];
#pragma unroll
                for (int nf = 0; nf < 4; nf++) {
                    int n = wn * 32 + nf * 8 + gid;
                    bf[nf][0] = Bs[kb + tig][n];
                    bf[nf][1] = Bs[kb + tig + 4][n];
                }
#pragma unroll
                for (int mf = 0; mf < 4; mf++)
#pragma unroll
                    for (int nf = 0; nf < 4; nf++)
                        MMA_TF32(acc[mf][nf], af[mf], bf[nf]);
            }
            __syncthreads();
        }

        // epilogue
        const GemmOut& po = p.o[o];
#pragma unroll
        for (int mf = 0; mf < 4; mf++) {
            int ra = row0 + wm * 64 + mf * 16 + gid;
            int rb = ra + 8;
#pragma unroll
            for (int nf = 0; nf < 4; nf++) {
                int c0 = wn * 32 + nf * 8 + tig * 2;
                if (ra < N) {
                    epi_apply(po, (size_t)ra * D + c0,     c0,     acc[mf][nf][0]);
                    epi_apply(po, (size_t)ra * D + c0 + 1, c0 + 1, acc[mf][nf][1]);
                }
                if (rb < N) {
                    epi_apply(po, (size_t)rb * D + c0,     c0,     acc[mf][nf][2]);
                    epi_apply(po, (size_t)rb * D + c0 + 1, c0 + 1, acc[mf][nf][3]);
                }
            }
        }
        if (o + 1 < NOUT) __syncthreads();
    }
}

// ---------------- small kernels ----------------
__global__ void combine_bias_kernel(
    const float* bzm, const float* bzs, const float* bias_z,
    const float* brm, const float* brs, const float* bias_r,
    const float* bhm, const float* bhs, const float* bias_h, float* cb) {
    int i = threadIdx.x;
    cb[i]         = bzm[i] + bzs[i] + bias_z[i];
    cb[D + i]     = brm[i] + brs[i] + bias_r[i];
    cb[2 * D + i] = bhm[i] + bhs[i] + bias_h[i];
}

__global__ void copy_kernel(const float* __restrict__ src, float* __restrict__ dst, int n4) {
    int i = blockIdx.x * blockDim.x + threadIdx.x;
    if (i < n4) ((float4*)dst)[i] = ((const float4*)src)[i];
}

// ---------------- edge scatter: m[dst] += t[src] * ew   (edge_index is int32) ----------------
__global__ void scatter_kernel(const int* __restrict__ ei, const float* __restrict__ ew,
                               const float* __restrict__ t, float* __restrict__ m, int E) {
    long long idx = (long long)blockIdx.x * blockDim.x + threadIdx.x;
    int e = (int)(idx >> 5);
    if (e >= E) return;
    int lane = (int)(idx & 31);
    int s = ei[e];
    int d = ei[(size_t)E + e];
    float w = ew[e];
    float4 v = *(const float4*)(t + (size_t)s * D + lane * 4);
    float4 r;
    r.x = v.x * w; r.y = v.y * w; r.z = v.z * w; r.w = v.w * w;
    float* p = m + (size_t)d * D + lane * 4;
    asm volatile("red.global.add.v4.f32 [%0], {%1,%2,%3,%4};"
                 :: "l"(p), "f"(r.x), "f"(r.y), "f"(r.z), "f"(r.w) : "memory");
}

// ---------------- head: attention gate + scale ----------------
__global__ void att_kernel(const float* __restrict__ h, const float* __restrict__ Wag,
                           const float* __restrict__ bag, float* __restrict__ out, int N) {
    long long idx = (long long)blockIdx.x * blockDim.x + threadIdx.x;
    int node = (int)(idx >> 5);
    if (node >= N) return;
    int lane = (int)(idx & 31);
    float4 hv = *(const float4*)(h + (size_t)node * D + lane * 4);
    float4 wv = *(const float4*)(Wag + lane * 4);
    float s = hv.x * wv.x + hv.y * wv.y + hv.z * wv.z + hv.w * wv.w;
#pragma unroll
    for (int o = 16; o > 0; o >>= 1) s += __shfl_xor_sync(0xFFFFFFFF, s, o);
    float att = sigf(s + bag[0]);
    float4 r;
    r.x = hv.x * att; r.y = hv.y * att; r.z = hv.z * att; r.w = hv.w * att;
    *(float4*)(out + (size_t)node * D + lane * 4) = r;
}

// ---------------- pooling (batch is int32) ----------------
__global__ void zero_pool_kernel(float* pmax, float* psum, float* cnt) {
    int i = blockIdx.x * blockDim.x + threadIdx.x;
    if (i < NGRAPH * D) { pmax[i] = 0.f; psum[i] = 0.f; }
    if (i < NGRAPH) cnt[i] = 0.f;
}

__global__ void pool_kernel(const float* __restrict__ h2, const int* __restrict__ batch,
                            float* __restrict__ pmax, float* __restrict__ psum,
                            float* __restrict__ cnt, int N) {
    long long idx = (long long)blockIdx.x * blockDim.x + threadIdx.x;
    int node = (int)(idx >> 5);
    if (node >= N) return;
    int lane = (int)(idx & 31);
    int g = batch[node];
    float4 v = *(const float4*)(h2 + (size_t)node * D + lane * 4);
    int* pm = (int*)(pmax + (size_t)g * D + lane * 4);
    atomicMax(pm + 0, __float_as_int(v.x));   // h2 >= 0 so int order == float order
    atomicMax(pm + 1, __float_as_int(v.y));
    atomicMax(pm + 2, __float_as_int(v.z));
    atomicMax(pm + 3, __float_as_int(v.w));
    float* ps = psum + (size_t)g * D + lane * 4;
    asm volatile("red.global.add.v4.f32 [%0], {%1,%2,%3,%4};"
                 :: "l"(ps), "f"(v.x), "f"(v.y), "f"(v.z), "f"(v.w) : "memory");
    if (lane == 0) atomicAdd(cnt + g, 1.0f);
}

// ---------------- final MLP ----------------
__global__ void mlp_kernel(const float* __restrict__ pmax, const float* __restrict__ psum,
                           const float* __restrict__ cnt,
                           const float* __restrict__ W1, const float* __restrict__ b1,
                           const float* __restrict__ W2, const float* __restrict__ b2,
                           float* __restrict__ out) {
    __shared__ float xp[2 * D];
    __shared__ float hid[D];
    int g = blockIdx.x;
    int t = threadIdx.x;  // 128 threads
    float c = fmaxf(cnt[g], 1.0f);
    xp[t]     = fmaxf(pmax[(size_t)g * D + t], 0.0f);
    xp[D + t] = psum[(size_t)g * D + t] / c;
    __syncthreads();
    float acc = b1[t];
#pragma unroll 8
    for (int j = 0; j < 2 * D; j++) acc += xp[j] * W1[(size_t)j * D + t];
    hid[t] = fmaxf(acc, 0.f);
    __syncthreads();
    if (t < NCLASS) {
        float o = b2[t];
#pragma unroll 8
        for (int k = 0; k < D; k++) o += hid[k] * W2[(size_t)k * NCLASS + t];
        out[(size_t)g * NCLASS + t] = o;
    }
}

// ---------------- host orchestration ----------------
extern "C" void kernel_launch(void* const* d_in, const int* in_sizes, int n_in,
                              void* d_out, int out_size) {
    const float* x     = (const float*)d_in[0];
    const int*   ei    = (const int*)d_in[1];    // int32 (jax x64 disabled)
    const int*   batch = (const int*)d_in[2];    // int32
    const float* ew    = (const float*)d_in[3];
    const float* Wa    = (const float*)d_in[4];
    const float *Wzm = (const float*)d_in[5],  *bzm = (const float*)d_in[6];
    const float *Wzs = (const float*)d_in[7],  *bzs = (const float*)d_in[8];
    const float *Wrm = (const float*)d_in[9],  *brm = (const float*)d_in[10];
    const float *Wrs = (const float*)d_in[11], *brs = (const float*)d_in[12];
    const float *Whm = (const float*)d_in[13], *bhm = (const float*)d_in[14];
    const float *Whs = (const float*)d_in[15], *bhs = (const float*)d_in[16];
    const float *Whg = (const float*)d_in[17], *bhg = (const float*)d_in[18];
    const float *Whl = (const float*)d_in[19], *bhl = (const float*)d_in[20];
    const float *bias_z = (const float*)d_in[21];
    const float *bias_r = (const float*)d_in[22];
    const float *bias_h = (const float*)d_in[23];
    const float *Wag = (const float*)d_in[24], *bag = (const float*)d_in[25];
    const float *Wae = (const float*)d_in[26], *bae = (const float*)d_in[27];
    const float *W1  = (const float*)d_in[28], *b1  = (const float*)d_in[29];
    const float *W2  = (const float*)d_in[30], *b2  = (const float*)d_in[31];
    float* out = (float*)d_out;

    const int N = in_sizes[0] / D;
    const int E = in_sizes[3];

    float *h, *t, *m, *z, *r, *ci, *gg, *cb, *pmax, *psum, *cnt;
    cudaGetSymbolAddress((void**)&h,  g_h);
    cudaGetSymbolAddress((void**)&t,  g_t);
    cudaGetSymbolAddress((void**)&m,  g_m);
    cudaGetSymbolAddress((void**)&z,  g_z);
    cudaGetSymbolAddress((void**)&r,  g_r);
    cudaGetSymbolAddress((void**)&ci, g_ci);
    cudaGetSymbolAddress((void**)&gg, g_g);
    cudaGetSymbolAddress((void**)&cb, g_cb);
    cudaGetSymbolAddress((void**)&pmax, g_pmax);
    cudaGetSymbolAddress((void**)&psum, g_psum);
    cudaGetSymbolAddress((void**)&cnt,  g_cnt);

    const float* cbz = cb;
    const float* cbr = cb + D;
    const float* cbh = cb + 2 * D;

    const int ND = N * D;
    const int n4 = ND / 4;
    const dim3 gg128((N + 127) / 128);

    combine_bias_kernel<<<1, D>>>(bzm, bzs, bias_z, brm, brs, bias_r, bhm, bhs, bias_h, cb);
    copy_kernel<<<(n4 + 255) / 256, 256>>>(x, h, n4);

    for (int layer = 0; layer < 3; layer++) {
        // K1 (A=h): t = h@Wa (also -> m for self-loops) ; zp = h@Wzs + cbz ; rp = h@Wrs + cbr
        {
            GemmParams p{};
            p.o[0] = { Wa,  nullptr, nullptr, m,       t, 6 };
            p.o[1] = { Wzs, cbz,     nullptr, nullptr, z, 0 };
            p.o[2] = { Wrs, cbr,     nullptr, nullptr, r, 0 };
            gemm_fused<3><<<gg128, 256>>>(h, p, N);
        }
        // m[dst] += t[src]*ew
        {
            long long work = (long long)E * 32;
            scatter_kernel<<<(unsigned)((work + 255) / 256), 256>>>(ei, ew, t, m, E);
        }
        // K2 (A=m): z = sig(m@Wzm + zp) ; rh = sig(m@Wrm + rp)*h ; ci = m@Whm + cbh
        {
            GemmParams p{};
            p.o[0] = { Wzm, nullptr, z, nullptr, z,  1 };
            p.o[1] = { Wrm, nullptr, r, h,       r,  2 };
            p.o[2] = { Whm, cbh,     nullptr, nullptr, ci, 0 };
            gemm_fused<3><<<gg128, 256>>>(m, p, N);
        }
        // K3 (A=rh): ci += rh@Whs
        {
            GemmParams p{};
            p.o[0] = { Whs, nullptr, nullptr, nullptr, ci, 3 };
            gemm_fused<1><<<gg128, 256>>>(r, p, N);
        }
        // K4 (A=ci): g1 = ci@Whl + bhl ; h = z*(g1*sig(ci@Whg + bhg)) + (1-z)*h
        {
            GemmParams p{};
            p.o[0] = { Whl, bhl, nullptr, nullptr, gg, 0 };
            p.o[1] = { Whg, bhg, gg,      z,       h,  4 };
            gemm_fused<2><<<gg128, 256>>>(ci, p, N);
        }
    }

    // attention gate: t = h * sigmoid(h @ Wag + bag)
    {
        long long work = (long long)N * 32;
        att_kernel<<<(unsigned)((work + 255) / 256), 256>>>(h, Wag, bag, t, N);
    }
    // m = relu(t @ Wae + bae)
    {
        GemmParams p{};
        p.o[0] = { Wae, bae, nullptr, nullptr, m, 5 };
        gemm_fused<1><<<gg128, 256>>>(t, p, N);
    }

    // pooling + MLP head
    zero_pool_kernel<<<(NGRAPH * D + 255) / 256, 256>>>(pmax, psum, cnt);
    {
        long long work = (long long)N * 32;
        pool_kernel<<<(unsigned)((work + 255) / 256), 256>>>(m, batch, pmax, psum, cnt, N);
    }
    mlp_kernel<<<NGRAPH, D>>>(pmax, psum, cnt, W1, b1, W2, b2, out);
}

// round 12
// speedup vs baseline: 2.0191x; 1.6438x over previous
#include <cuda_runtime.h>
#include <cstdint>

#define D 128
#define NN_MAX 50000
#define NGRAPH 64
#define NCLASS 16

// ---------------- device scratch (allocation-free) ----------------
__device__ __align__(256) float g_h [NN_MAX * D];
__device__ __align__(256) float g_t [NN_MAX * D];
__device__ __align__(256) float g_m [NN_MAX * D];
__device__ __align__(256) float g_z [NN_MAX * D];
__device__ __align__(256) float g_r [NN_MAX * D];
__device__ __align__(256) float g_ci[NN_MAX * D];
__device__ __align__(256) float g_g [NN_MAX * D];
__device__ __align__(256) float g_cb[3 * D];     // combined biases: z, r, h
__device__ __align__(256) float g_pmax[NGRAPH * D];
__device__ __align__(256) float g_psum[NGRAPH * D];
__device__ __align__(256) float g_cnt [NGRAPH];

__device__ __forceinline__ float sigf(float x) { return 1.0f / (1.0f + __expf(-x)); }

__device__ __forceinline__ uint32_t to_tf32(float f) {
    uint32_t u;
    asm("cvt.rna.tf32.f32 %0, %1;" : "=r"(u) : "f"(f));
    return u;
}

// ---------------- fused multi-output TF32 tensor-core GEMM (M=64 tiles) ----------------
// modes: 0: out = acc (+bias)   1: out = sigmoid(acc + aux1[idx])
//        2: r = sigmoid(acc+aux1[idx]); out = r*aux2[idx]
//        3: out[idx] += acc     4: g2 = acc+bias[col]; out = aux2*(aux1*sigf(g2)) + (1-aux2)*out
//        5: out = relu(acc + bias)
struct GemmOut {
    const float* W;
    const float* bias;
    const float* aux1;
    const float* aux2;
    float* out;
    int mode;
};
struct GemmParams { GemmOut o[3]; };

__device__ __forceinline__ void epi_apply(const GemmOut& o, size_t idx, int col, float v) {
    switch (o.mode) {
    case 0: if (o.bias) v += o.bias[col]; o.out[idx] = v; break;
    case 1: o.out[idx] = sigf(v + o.aux1[idx]); break;
    case 2: { float r = sigf(v + o.aux1[idx]); o.out[idx] = r * o.aux2[idx]; } break;
    case 3: o.out[idx] += v; break;
    case 4: { float g2 = v + o.bias[col]; float g1 = o.aux1[idx]; float zz = o.aux2[idx];
              o.out[idx] = zz * (g1 * sigf(g2)) + (1.f - zz) * o.out[idx]; } break;
    case 5: v += o.bias[col]; o.out[idx] = fmaxf(v, 0.f); break;
    }
}

#define MMA_TF32(c, a, b) \
    asm volatile("mma.sync.aligned.m16n8k8.row.col.f32.tf32.tf32.f32 " \
        "{%0,%1,%2,%3}, {%4,%5,%6,%7}, {%8,%9}, {%0,%1,%2,%3};" \
        : "+f"((c)[0]), "+f"((c)[1]), "+f"((c)[2]), "+f"((c)[3]) \
        : "r"((a)[0]), "r"((a)[1]), "r"((a)[2]), "r"((a)[3]), "r"((b)[0]), "r"((b)[1]))

template<int NOUT>
__global__ void __launch_bounds__(256) gemm_fused(const float* __restrict__ A, GemmParams p, int N)
{
    __shared__ uint32_t As[64][36];    // [row][k-chunk], pad 4 -> conflict-free A-frag loads
    __shared__ uint32_t Bs[32][132];   // [k][n],  pad 4 -> coalesced stores, ~2-way frag loads

    const int tid  = threadIdx.x;
    const int lane = tid & 31;
    const int wid  = tid >> 5;
    const int wm   = wid >> 2;          // 0..1 -> m offset wm*32
    const int wn   = wid & 3;           // 0..3 -> n offset wn*32
    const int row0 = blockIdx.x * 64;
    const int gid  = lane >> 2;         // groupID 0..7
    const int tig  = lane & 3;          // thread-in-group 0..3

    for (int o = 0; o < NOUT; o++) {
        const float* __restrict__ W = p.o[o].W;
        float acc[2][4][4];             // [mfrag][nfrag][reg]
#pragma unroll
        for (int mf = 0; mf < 2; mf++)
#pragma unroll
            for (int nf = 0; nf < 4; nf++)
#pragma unroll
                for (int q = 0; q < 4; q++) acc[mf][nf][q] = 0.f;

        for (int kc = 0; kc < D; kc += 32) {
            // A chunk: 64 rows x 32 k  (512 float4; 2 per thread)
#pragma unroll
            for (int i = 0; i < 2; i++) {
                int f = tid + i * 256;
                int r = f >> 3, kg = (f & 7) * 4;
                int grow = row0 + r;
                float4 v = make_float4(0.f, 0.f, 0.f, 0.f);
                if (grow < N) v = *(const float4*)&A[(size_t)grow * D + kc + kg];
                As[r][kg + 0] = to_tf32(v.x); As[r][kg + 1] = to_tf32(v.y);
                As[r][kg + 2] = to_tf32(v.z); As[r][kg + 3] = to_tf32(v.w);
            }
            // W chunk: 32 k-rows x 128 n  (1024 float4; 4 per thread), k-major as-is
#pragma unroll
            for (int i = 0; i < 4; i++) {
                int f = tid + i * 256;
                int k = f >> 5, ng = (f & 31) * 4;
                float4 v = *(const float4*)&W[(size_t)(kc + k) * D + ng];
                Bs[k][ng + 0] = to_tf32(v.x); Bs[k][ng + 1] = to_tf32(v.y);
                Bs[k][ng + 2] = to_tf32(v.z); Bs[k][ng + 3] = to_tf32(v.w);
            }
            __syncthreads();

#pragma unroll
            for (int k8 = 0; k8 < 4; k8++) {
                const int kb = k8 * 8;
                uint32_t af[2][4];
#pragma unroll
                for (int mf = 0; mf < 2; mf++) {
                    int r = wm * 32 + mf * 16 + gid;
                    af[mf][0] = As[r][kb + tig];
                    af[mf][1] = As[r + 8][kb + tig];
                    af[mf][2] = As[r][kb + tig + 4];
                    af[mf][3] = As[r + 8][kb + tig + 4];
                }
                uint32_t bf[4][2];
#pragma unroll
                for (int nf = 0; nf < 4; nf++) {
                    int n = wn * 32 + nf * 8 + gid;
                    bf[nf][0] = Bs[kb + tig][n];
                    bf[nf][1] = Bs[kb + tig + 4][n];
                }
#pragma unroll
                for (int mf = 0; mf < 2; mf++)
#pragma unroll
                    for (int nf = 0; nf < 4; nf++)
                        MMA_TF32(acc[mf][nf], af[mf], bf[nf]);
            }
            __syncthreads();
        }

        // epilogue
        const GemmOut& po = p.o[o];
#pragma unroll
        for (int mf = 0; mf < 2; mf++) {
            int ra = row0 + wm * 32 + mf * 16 + gid;
            int rb = ra + 8;
#pragma unroll
            for (int nf = 0; nf < 4; nf++) {
                int c0 = wn * 32 + nf * 8 + tig * 2;
                if (ra < N) {
                    epi_apply(po, (size_t)ra * D + c0,     c0,     acc[mf][nf][0]);
                    epi_apply(po, (size_t)ra * D + c0 + 1, c0 + 1, acc[mf][nf][1]);
                }
                if (rb < N) {
                    epi_apply(po, (size_t)rb * D + c0,     c0,     acc[mf][nf][2]);
                    epi_apply(po, (size_t)rb * D + c0 + 1, c0 + 1, acc[mf][nf][3]);
                }
            }
        }
        if (o + 1 < NOUT) __syncthreads();
    }
}

// ---------------- small kernels ----------------
__global__ void combine_bias_kernel(
    const float* bzm, const float* bzs, const float* bias_z,
    const float* brm, const float* brs, const float* bias_r,
    const float* bhm, const float* bhs, const float* bias_h, float* cb) {
    int i = threadIdx.x;
    cb[i]         = bzm[i] + bzs[i] + bias_z[i];
    cb[D + i]     = brm[i] + brs[i] + bias_r[i];
    cb[2 * D + i] = bhm[i] + bhs[i] + bias_h[i];
}

__global__ void copy_kernel(const float* __restrict__ src, float* __restrict__ dst, int n4) {
    int i = blockIdx.x * blockDim.x + threadIdx.x;
    if (i < n4) ((float4*)dst)[i] = ((const float4*)src)[i];
}

// ---------------- edge scatter: m[dst] += t[src] * ew   (edge_index is int32) ----------------
__global__ void scatter_kernel(const int* __restrict__ ei, const float* __restrict__ ew,
                               const float* __restrict__ t, float* __restrict__ m, int E) {
    long long idx = (long long)blockIdx.x * blockDim.x + threadIdx.x;
    int e = (int)(idx >> 5);
    if (e >= E) return;
    int lane = (int)(idx & 31);
    int s = ei[e];
    int d = ei[(size_t)E + e];
    float w = ew[e];
    float4 v = *(const float4*)(t + (size_t)s * D + lane * 4);
    float4 r;
    r.x = v.x * w; r.y = v.y * w; r.z = v.z * w; r.w = v.w * w;
    float* p = m + (size_t)d * D + lane * 4;
    asm volatile("red.global.add.v4.f32 [%0], {%1,%2,%3,%4};"
                 :: "l"(p), "f"(r.x), "f"(r.y), "f"(r.z), "f"(r.w) : "memory");
}

// ---------------- head: attention gate + scale ----------------
__global__ void att_kernel(const float* __restrict__ h, const float* __restrict__ Wag,
                           const float* __restrict__ bag, float* __restrict__ out, int N) {
    long long idx = (long long)blockIdx.x * blockDim.x + threadIdx.x;
    int node = (int)(idx >> 5);
    if (node >= N) return;
    int lane = (int)(idx & 31);
    float4 hv = *(const float4*)(h + (size_t)node * D + lane * 4);
    float4 wv = *(const float4*)(Wag + lane * 4);
    float s = hv.x * wv.x + hv.y * wv.y + hv.z * wv.z + hv.w * wv.w;
#pragma unroll
    for (int o = 16; o > 0; o >>= 1) s += __shfl_xor_sync(0xFFFFFFFF, s, o);
    float att = sigf(s + bag[0]);
    float4 r;
    r.x = hv.x * att; r.y = hv.y * att; r.z = hv.z * att; r.w = hv.w * att;
    *(float4*)(out + (size_t)node * D + lane * 4) = r;
}

// ---------------- pooling (batch is int32) ----------------
__global__ void zero_pool_kernel(float* pmax, float* psum, float* cnt) {
    int i = blockIdx.x * blockDim.x + threadIdx.x;
    if (i < NGRAPH * D) { pmax[i] = 0.f; psum[i] = 0.f; }
    if (i < NGRAPH) cnt[i] = 0.f;
}

__global__ void pool_kernel(const float* __restrict__ h2, const int* __restrict__ batch,
                            float* __restrict__ pmax, float* __restrict__ psum,
                            float* __restrict__ cnt, int N) {
    long long idx = (long long)blockIdx.x * blockDim.x + threadIdx.x;
    int node = (int)(idx >> 5);
    if (node >= N) return;
    int lane = (int)(idx & 31);
    int g = batch[node];
    float4 v = *(const float4*)(h2 + (size_t)node * D + lane * 4);
    int* pm = (int*)(pmax + (size_t)g * D + lane * 4);
    atomicMax(pm + 0, __float_as_int(v.x));   // h2 >= 0 so int order == float order
    atomicMax(pm + 1, __float_as_int(v.y));
    atomicMax(pm + 2, __float_as_int(v.z));
    atomicMax(pm + 3, __float_as_int(v.w));
    float* ps = psum + (size_t)g * D + lane * 4;
    asm volatile("red.global.add.v4.f32 [%0], {%1,%2,%3,%4};"
                 :: "l"(ps), "f"(v.x), "f"(v.y), "f"(v.z), "f"(v.w) : "memory");
    if (lane == 0) atomicAdd(cnt + g, 1.0f);
}

// ---------------- final MLP ----------------
__global__ void mlp_kernel(const float* __restrict__ pmax, const float* __restrict__ psum,
                           const float* __restrict__ cnt,
                           const float* __restrict__ W1, const float* __restrict__ b1,
                           const float* __restrict__ W2, const float* __restrict__ b2,
                           float* __restrict__ out) {
    __shared__ float xp[2 * D];
    __shared__ float hid[D];
    int g = blockIdx.x;
    int t = threadIdx.x;  // 128 threads
    float c = fmaxf(cnt[g], 1.0f);
    xp[t]     = fmaxf(pmax[(size_t)g * D + t], 0.0f);
    xp[D + t] = psum[(size_t)g * D + t] / c;
    __syncthreads();
    float acc = b1[t];
#pragma unroll 8
    for (int j = 0; j < 2 * D; j++) acc += xp[j] * W1[(size_t)j * D + t];
    hid[t] = fmaxf(acc, 0.f);
    __syncthreads();
    if (t < NCLASS) {
        float o = b2[t];
#pragma unroll 8
        for (int k = 0; k < D; k++) o += hid[k] * W2[(size_t)k * NCLASS + t];
        out[(size_t)g * NCLASS + t] = o;
    }
}

// ---------------- host orchestration ----------------
extern "C" void kernel_launch(void* const* d_in, const int* in_sizes, int n_in,
                              void* d_out, int out_size) {
    const float* x     = (const float*)d_in[0];
    const int*   ei    = (const int*)d_in[1];    // int32 (jax x64 disabled)
    const int*   batch = (const int*)d_in[2];    // int32
    const float* ew    = (const float*)d_in[3];
    const float* Wa    = (const float*)d_in[4];
    const float *Wzm = (const float*)d_in[5],  *bzm = (const float*)d_in[6];
    const float *Wzs = (const float*)d_in[7],  *bzs = (const float*)d_in[8];
    const float *Wrm = (const float*)d_in[9],  *brm = (const float*)d_in[10];
    const float *Wrs = (const float*)d_in[11], *brs = (const float*)d_in[12];
    const float *Whm = (const float*)d_in[13], *bhm = (const float*)d_in[14];
    const float *Whs = (const float*)d_in[15], *bhs = (const float*)d_in[16];
    const float *Whg = (const float*)d_in[17], *bhg = (const float*)d_in[18];
    const float *Whl = (const float*)d_in[19], *bhl = (const float*)d_in[20];
    const float *bias_z = (const float*)d_in[21];
    const float *bias_r = (const float*)d_in[22];
    const float *bias_h = (const float*)d_in[23];
    const float *Wag = (const float*)d_in[24], *bag = (const float*)d_in[25];
    const float *Wae = (const float*)d_in[26], *bae = (const float*)d_in[27];
    const float *W1  = (const float*)d_in[28], *b1  = (const float*)d_in[29];
    const float *W2  = (const float*)d_in[30], *b2  = (const float*)d_in[31];
    float* out = (float*)d_out;

    const int N = in_sizes[0] / D;
    const int E = in_sizes[3];

    float *h, *t, *m, *z, *r, *ci, *gg, *cb, *pmax, *psum, *cnt;
    cudaGetSymbolAddress((void**)&h,  g_h);
    cudaGetSymbolAddress((void**)&t,  g_t);
    cudaGetSymbolAddress((void**)&m,  g_m);
    cudaGetSymbolAddress((void**)&z,  g_z);
    cudaGetSymbolAddress((void**)&r,  g_r);
    cudaGetSymbolAddress((void**)&ci, g_ci);
    cudaGetSymbolAddress((void**)&gg, g_g);
    cudaGetSymbolAddress((void**)&cb, g_cb);
    cudaGetSymbolAddress((void**)&pmax, g_pmax);
    cudaGetSymbolAddress((void**)&psum, g_psum);
    cudaGetSymbolAddress((void**)&cnt,  g_cnt);

    const float* cbz = cb;
    const float* cbr = cb + D;
    const float* cbh = cb + 2 * D;

    const int ND = N * D;
    const int n4 = ND / 4;
    const dim3 gg64((N + 63) / 64);

    combine_bias_kernel<<<1, D>>>(bzm, bzs, bias_z, brm, brs, bias_r, bhm, bhs, bias_h, cb);
    copy_kernel<<<(n4 + 255) / 256, 256>>>(x, h, n4);

    for (int layer = 0; layer < 3; layer++) {
        // K1 (A=h): t = h@Wa ; zp = h@Wzs + cbz ; rp = h@Wrs + cbr
        {
            GemmParams p{};
            p.o[0] = { Wa,  nullptr, nullptr, nullptr, t, 0 };
            p.o[1] = { Wzs, cbz,     nullptr, nullptr, z, 0 };
            p.o[2] = { Wrs, cbr,     nullptr, nullptr, r, 0 };
            gemm_fused<3><<<gg64, 256>>>(h, p, N);
        }
        // m = t (self loops), then m[dst] += t[src]*ew
        copy_kernel<<<(n4 + 255) / 256, 256>>>(t, m, n4);
        {
            long long work = (long long)E * 32;
            scatter_kernel<<<(unsigned)((work + 255) / 256), 256>>>(ei, ew, t, m, E);
        }
        // K2 (A=m): z = sig(m@Wzm + zp) ; rh = sig(m@Wrm + rp)*h ; ci = m@Whm + cbh
        {
            GemmParams p{};
            p.o[0] = { Wzm, nullptr, z, nullptr, z,  1 };
            p.o[1] = { Wrm, nullptr, r, h,       r,  2 };
            p.o[2] = { Whm, cbh,     nullptr, nullptr, ci, 0 };
            gemm_fused<3><<<gg64, 256>>>(m, p, N);
        }
        // K3 (A=rh): ci += rh@Whs
        {
            GemmParams p{};
            p.o[0] = { Whs, nullptr, nullptr, nullptr, ci, 3 };
            gemm_fused<1><<<gg64, 256>>>(r, p, N);
        }
        // K4 (A=ci): g1 = ci@Whl + bhl ; h = z*(g1*sig(ci@Whg + bhg)) + (1-z)*h
        {
            GemmParams p{};
            p.o[0] = { Whl, bhl, nullptr, nullptr, gg, 0 };
            p.o[1] = { Whg, bhg, gg,      z,       h,  4 };
            gemm_fused<2><<<gg64, 256>>>(ci, p, N);
        }
    }

    // attention gate: t = h * sigmoid(h @ Wag + bag)
    {
        long long work = (long long)N * 32;
        att_kernel<<<(unsigned)((work + 255) / 256), 256>>>(h, Wag, bag, t, N);
    }
    // m = relu(t @ Wae + bae)
    {
        GemmParams p{};
        p.o[0] = { Wae, bae, nullptr, nullptr, m, 5 };
        gemm_fused<1><<<gg64, 256>>>(t, p, N);
    }

    // pooling + MLP head
    zero_pool_kernel<<<(NGRAPH * D + 255) / 256, 256>>>(pmax, psum, cnt);
    {
        long long work = (long long)N * 32;
        pool_kernel<<<(unsigned)((work + 255) / 256), 256>>>(m, batch, pmax, psum, cnt, N);
    }
    mlp_kernel<<<NGRAPH, D>>>(pmax, psum, cnt, W1, b1, W2, b2, out);
}

// round 14
// speedup vs baseline: 2.2497x; 1.1142x over previous
#include <cuda_runtime.h>
#include <cstdint>

#define D 128
#define NN_MAX 50000
#define NGRAPH 64
#define NCLASS 16

// ---------------- device scratch (allocation-free) ----------------
__device__ __align__(256) float g_h [NN_MAX * D];
__device__ __align__(256) float g_t [NN_MAX * D];
__device__ __align__(256) float g_m [NN_MAX * D];
__device__ __align__(256) float g_z [NN_MAX * D];
__device__ __align__(256) float g_r [NN_MAX * D];
__device__ __align__(256) float g_ci[NN_MAX * D];
__device__ __align__(256) float g_g [NN_MAX * D];
__device__ __align__(256) float g_cb[3 * D];     // combined biases: z, r, h
__device__ __align__(256) float g_pmax[NGRAPH * D];
__device__ __align__(256) float g_psum[NGRAPH * D];
__device__ __align__(256) float g_cnt [NGRAPH];

__device__ __forceinline__ float sigf(float x) { return 1.0f / (1.0f + __expf(-x)); }

__device__ __forceinline__ uint32_t to_tf32(float f) {
    uint32_t u;
    asm("cvt.rna.tf32.f32 %0, %1;" : "=r"(u) : "f"(f));
    return u;
}

// ---------------- fused multi-output TF32 tensor-core GEMM ----------------
// M=64 tiles; full-K A staged ONCE per CTA; W chunks staged per output.
// modes: 0: out = acc (+bias)   1: out = sigmoid(acc + aux1[idx])
//        2: r = sigmoid(acc+aux1[idx]); out = r*aux2[idx]
//        3: out[idx] += acc     4: g2 = acc+bias[col]; out = aux2*(aux1*sigf(g2)) + (1-aux2)*out
//        5: out = relu(acc + bias)
struct GemmOut {
    const float* W;
    const float* bias;
    const float* aux1;
    const float* aux2;
    float* out;
    int mode;
};
struct GemmParams { GemmOut o[3]; };

__device__ __forceinline__ void epi_apply(const GemmOut& o, size_t idx, int col, float v) {
    switch (o.mode) {
    case 0: if (o.bias) v += o.bias[col]; o.out[idx] = v; break;
    case 1: o.out[idx] = sigf(v + o.aux1[idx]); break;
    case 2: { float r = sigf(v + o.aux1[idx]); o.out[idx] = r * o.aux2[idx]; } break;
    case 3: o.out[idx] += v; break;
    case 4: { float g2 = v + o.bias[col]; float g1 = o.aux1[idx]; float zz = o.aux2[idx];
              o.out[idx] = zz * (g1 * sigf(g2)) + (1.f - zz) * o.out[idx]; } break;
    case 5: v += o.bias[col]; o.out[idx] = fmaxf(v, 0.f); break;
    }
}

#define MMA_TF32(c, a, b) \
    asm volatile("mma.sync.aligned.m16n8k8.row.col.f32.tf32.tf32.f32 " \
        "{%0,%1,%2,%3}, {%4,%5,%6,%7}, {%8,%9}, {%0,%1,%2,%3};" \
        : "+f"((c)[0]), "+f"((c)[1]), "+f"((c)[2]), "+f"((c)[3]) \
        : "r"((a)[0]), "r"((a)[1]), "r"((a)[2]), "r"((a)[3]), "r"((b)[0]), "r"((b)[1]))

#define AS_STRIDE 132
#define BS_STRIDE 132
#define AS_WORDS (64 * AS_STRIDE)
#define BS_WORDS (32 * BS_STRIDE)
#define GEMM_SMEM_BYTES ((AS_WORDS + BS_WORDS) * 4)   // 50,688 bytes

template<int NOUT>
__global__ void __launch_bounds__(256) gemm_fused(const float* __restrict__ A, GemmParams p, int N)
{
    extern __shared__ uint32_t smem[];
    uint32_t (*As)[AS_STRIDE] = (uint32_t (*)[AS_STRIDE])smem;             // [64][132] full-K
    uint32_t (*Bs)[BS_STRIDE] = (uint32_t (*)[BS_STRIDE])(smem + AS_WORDS);// [32][132]

    const int tid  = threadIdx.x;
    const int lane = tid & 31;
    const int wid  = tid >> 5;
    const int wm   = wid >> 2;          // 0..1 -> m offset wm*32
    const int wn   = wid & 3;           // 0..3 -> n offset wn*32
    const int row0 = blockIdx.x * 64;
    const int gid  = lane >> 2;         // groupID 0..7
    const int tig  = lane & 3;          // thread-in-group 0..3

    // ---- stage full-K A once per CTA: 64 rows x 128 cols = 2048 float4, 8 per thread ----
#pragma unroll
    for (int i = 0; i < 8; i++) {
        int f = tid + i * 256;              // 0..2047
        int r = f >> 5, kg = (f & 31) * 4;  // r 0..63, kg 0..124
        int grow = row0 + r;
        float4 v = make_float4(0.f, 0.f, 0.f, 0.f);
        if (grow < N) v = *(const float4*)&A[(size_t)grow * D + kg];
        As[r][kg + 0] = to_tf32(v.x); As[r][kg + 1] = to_tf32(v.y);
        As[r][kg + 2] = to_tf32(v.z); As[r][kg + 3] = to_tf32(v.w);
    }

    for (int o = 0; o < NOUT; o++) {
        const float* __restrict__ W = p.o[o].W;
        float acc[2][4][4];             // [mfrag][nfrag][reg]
#pragma unroll
        for (int mf = 0; mf < 2; mf++)
#pragma unroll
            for (int nf = 0; nf < 4; nf++)
#pragma unroll
                for (int q = 0; q < 4; q++) acc[mf][nf][q] = 0.f;

        for (int kc = 0; kc < D; kc += 32) {
            // W chunk: 32 k-rows x 128 n  (1024 float4; 4 per thread), k-major as-is
#pragma unroll
            for (int i = 0; i < 4; i++) {
                int f = tid + i * 256;
                int k = f >> 5, ng = (f & 31) * 4;
                float4 v = *(const float4*)&W[(size_t)(kc + k) * D + ng];
                Bs[k][ng + 0] = to_tf32(v.x); Bs[k][ng + 1] = to_tf32(v.y);
                Bs[k][ng + 2] = to_tf32(v.z); Bs[k][ng + 3] = to_tf32(v.w);
            }
            __syncthreads();

#pragma unroll
            for (int k8 = 0; k8 < 4; k8++) {
                const int kb = kc + k8 * 8;
                uint32_t af[2][4];
#pragma unroll
                for (int mf = 0; mf < 2; mf++) {
                    int r = wm * 32 + mf * 16 + gid;
                    af[mf][0] = As[r][kb + tig];
                    af[mf][1] = As[r + 8][kb + tig];
                    af[mf][2] = As[r][kb + tig + 4];
                    af[mf][3] = As[r + 8][kb + tig + 4];
                }
                uint32_t bf[4][2];
#pragma unroll
                for (int nf = 0; nf < 4; nf++) {
                    int n = wn * 32 + nf * 8 + gid;
                    bf[nf][0] = Bs[k8 * 8 + tig][n];
                    bf[nf][1] = Bs[k8 * 8 + tig + 4][n];
                }
#pragma unroll
                for (int mf = 0; mf < 2; mf++)
#pragma unroll
                    for (int nf = 0; nf < 4; nf++)
                        MMA_TF32(acc[mf][nf], af[mf], bf[nf]);
            }
            __syncthreads();
        }

        // epilogue
        const GemmOut& po = p.o[o];
#pragma unroll
        for (int mf = 0; mf < 2; mf++) {
            int ra = row0 + wm * 32 + mf * 16 + gid;
            int rb = ra + 8;
#pragma unroll
            for (int nf = 0; nf < 4; nf++) {
                int c0 = wn * 32 + nf * 8 + tig * 2;
                if (ra < N) {
                    epi_apply(po, (size_t)ra * D + c0,     c0,     acc[mf][nf][0]);
                    epi_apply(po, (size_t)ra * D + c0 + 1, c0 + 1, acc[mf][nf][1]);
                }
                if (rb < N) {
                    epi_apply(po, (size_t)rb * D + c0,     c0,     acc[mf][nf][2]);
                    epi_apply(po, (size_t)rb * D + c0 + 1, c0 + 1, acc[mf][nf][3]);
                }
            }
        }
        if (o + 1 < NOUT) __syncthreads();
    }
}

// ---------------- small kernels ----------------
__global__ void combine_bias_kernel(
    const float* bzm, const float* bzs, const float* bias_z,
    const float* brm, const float* brs, const float* bias_r,
    const float* bhm, const float* bhs, const float* bias_h, float* cb) {
    int i = threadIdx.x;
    cb[i]         = bzm[i] + bzs[i] + bias_z[i];
    cb[D + i]     = brm[i] + brs[i] + bias_r[i];
    cb[2 * D + i] = bhm[i] + bhs[i] + bias_h[i];
}

__global__ void copy_kernel(const float* __restrict__ src, float* __restrict__ dst, int n4) {
    int i = blockIdx.x * blockDim.x + threadIdx.x;
    if (i < n4) ((float4*)dst)[i] = ((const float4*)src)[i];
}

// ---------------- edge scatter: m[dst] += t[src] * ew   (edge_index is int32) ----------------
__global__ void scatter_kernel(const int* __restrict__ ei, const float* __restrict__ ew,
                               const float* __restrict__ t, float* __restrict__ m, int E) {
    long long idx = (long long)blockIdx.x * blockDim.x + threadIdx.x;
    int e = (int)(idx >> 5);
    if (e >= E) return;
    int lane = (int)(idx & 31);
    int s = ei[e];
    int d = ei[(size_t)E + e];
    float w = ew[e];
    float4 v = *(const float4*)(t + (size_t)s * D + lane * 4);
    float4 r;
    r.x = v.x * w; r.y = v.y * w; r.z = v.z * w; r.w = v.w * w;
    float* p = m + (size_t)d * D + lane * 4;
    asm volatile("red.global.add.v4.f32 [%0], {%1,%2,%3,%4};"
                 :: "l"(p), "f"(r.x), "f"(r.y), "f"(r.z), "f"(r.w) : "memory");
}

// ---------------- head: attention gate + scale ----------------
__global__ void att_kernel(const float* __restrict__ h, const float* __restrict__ Wag,
                           const float* __restrict__ bag, float* __restrict__ out, int N) {
    long long idx = (long long)blockIdx.x * blockDim.x + threadIdx.x;
    int node = (int)(idx >> 5);
    if (node >= N) return;
    int lane = (int)(idx & 31);
    float4 hv = *(const float4*)(h + (size_t)node * D + lane * 4);
    float4 wv = *(const float4*)(Wag + lane * 4);
    float s = hv.x * wv.x + hv.y * wv.y + hv.z * wv.z + hv.w * wv.w;
#pragma unroll
    for (int o = 16; o > 0; o >>= 1) s += __shfl_xor_sync(0xFFFFFFFF, s, o);
    float att = sigf(s + bag[0]);
    float4 r;
    r.x = hv.x * att; r.y = hv.y * att; r.z = hv.z * att; r.w = hv.w * att;
    *(float4*)(out + (size_t)node * D + lane * 4) = r;
}

// ---------------- pooling (batch is int32) ----------------
__global__ void zero_pool_kernel(float* pmax, float* psum, float* cnt) {
    int i = blockIdx.x * blockDim.x + threadIdx.x;
    if (i < NGRAPH * D) { pmax[i] = 0.f; psum[i] = 0.f; }
    if (i < NGRAPH) cnt[i] = 0.f;
}

__global__ void pool_kernel(const float* __restrict__ h2, const int* __restrict__ batch,
                            float* __restrict__ pmax, float* __restrict__ psum,
                            float* __restrict__ cnt, int N) {
    long long idx = (long long)blockIdx.x * blockDim.x + threadIdx.x;
    int node = (int)(idx >> 5);
    if (node >= N) return;
    int lane = (int)(idx & 31);
    int g = batch[node];
    float4 v = *(const float4*)(h2 + (size_t)node * D + lane * 4);
    int* pm = (int*)(pmax + (size_t)g * D + lane * 4);
    atomicMax(pm + 0, __float_as_int(v.x));   // h2 >= 0 so int order == float order
    atomicMax(pm + 1, __float_as_int(v.y));
    atomicMax(pm + 2, __float_as_int(v.z));
    atomicMax(pm + 3, __float_as_int(v.w));
    float* ps = psum + (size_t)g * D + lane * 4;
    asm volatile("red.global.add.v4.f32 [%0], {%1,%2,%3,%4};"
                 :: "l"(ps), "f"(v.x), "f"(v.y), "f"(v.z), "f"(v.w) : "memory");
    if (lane == 0) atomicAdd(cnt + g, 1.0f);
}

// ---------------- final MLP ----------------
__global__ void mlp_kernel(const float* __restrict__ pmax, const float* __restrict__ psum,
                           const float* __restrict__ cnt,
                           const float* __restrict__ W1, const float* __restrict__ b1,
                           const float* __restrict__ W2, const float* __restrict__ b2,
                           float* __restrict__ out) {
    __shared__ float xp[2 * D];
    __shared__ float hid[D];
    int g = blockIdx.x;
    int t = threadIdx.x;  // 128 threads
    float c = fmaxf(cnt[g], 1.0f);
    xp[t]     = fmaxf(pmax[(size_t)g * D + t], 0.0f);
    xp[D + t] = psum[(size_t)g * D + t] / c;
    __syncthreads();
    float acc = b1[t];
#pragma unroll 8
    for (int j = 0; j < 2 * D; j++) acc += xp[j] * W1[(size_t)j * D + t];
    hid[t] = fmaxf(acc, 0.f);
    __syncthreads();
    if (t < NCLASS) {
        float o = b2[t];
#pragma unroll 8
        for (int k = 0; k < D; k++) o += hid[k] * W2[(size_t)k * NCLASS + t];
        out[(size_t)g * NCLASS + t] = o;
    }
}

// ---------------- host orchestration ----------------
extern "C" void kernel_launch(void* const* d_in, const int* in_sizes, int n_in,
                              void* d_out, int out_size) {
    const float* x     = (const float*)d_in[0];
    const int*   ei    = (const int*)d_in[1];    // int32 (jax x64 disabled)
    const int*   batch = (const int*)d_in[2];    // int32
    const float* ew    = (const float*)d_in[3];
    const float* Wa    = (const float*)d_in[4];
    const float *Wzm = (const float*)d_in[5],  *bzm = (const float*)d_in[6];
    const float *Wzs = (const float*)d_in[7],  *bzs = (const float*)d_in[8];
    const float *Wrm = (const float*)d_in[9],  *brm = (const float*)d_in[10];
    const float *Wrs = (const float*)d_in[11], *brs = (const float*)d_in[12];
    const float *Whm = (const float*)d_in[13], *bhm = (const float*)d_in[14];
    const float *Whs = (const float*)d_in[15], *bhs = (const float*)d_in[16];
    const float *Whg = (const float*)d_in[17], *bhg = (const float*)d_in[18];
    const float *Whl = (const float*)d_in[19], *bhl = (const float*)d_in[20];
    const float *bias_z = (const float*)d_in[21];
    const float *bias_r = (const float*)d_in[22];
    const float *bias_h = (const float*)d_in[23];
    const float *Wag = (const float*)d_in[24], *bag = (const float*)d_in[25];
    const float *Wae = (const float*)d_in[26], *bae = (const float*)d_in[27];
    const float *W1  = (const float*)d_in[28], *b1  = (const float*)d_in[29];
    const float *W2  = (const float*)d_in[30], *b2  = (const float*)d_in[31];
    float* out = (float*)d_out;

    const int N = in_sizes[0] / D;
    const int E = in_sizes[3];

    float *h, *t, *m, *z, *r, *ci, *gg, *cb, *pmax, *psum, *cnt;
    cudaGetSymbolAddress((void**)&h,  g_h);
    cudaGetSymbolAddress((void**)&t,  g_t);
    cudaGetSymbolAddress((void**)&m,  g_m);
    cudaGetSymbolAddress((void**)&z,  g_z);
    cudaGetSymbolAddress((void**)&r,  g_r);
    cudaGetSymbolAddress((void**)&ci, g_ci);
    cudaGetSymbolAddress((void**)&gg, g_g);
    cudaGetSymbolAddress((void**)&cb, g_cb);
    cudaGetSymbolAddress((void**)&pmax, g_pmax);
    cudaGetSymbolAddress((void**)&psum, g_psum);
    cudaGetSymbolAddress((void**)&cnt,  g_cnt);

    cudaFuncSetAttribute(gemm_fused<1>, cudaFuncAttributeMaxDynamicSharedMemorySize, GEMM_SMEM_BYTES);
    cudaFuncSetAttribute(gemm_fused<2>, cudaFuncAttributeMaxDynamicSharedMemorySize, GEMM_SMEM_BYTES);
    cudaFuncSetAttribute(gemm_fused<3>, cudaFuncAttributeMaxDynamicSharedMemorySize, GEMM_SMEM_BYTES);

    const float* cbz = cb;
    const float* cbr = cb + D;
    const float* cbh = cb + 2 * D;

    const int ND = N * D;
    const int n4 = ND / 4;
    const dim3 gg64((N + 63) / 64);

    combine_bias_kernel<<<1, D>>>(bzm, bzs, bias_z, brm, brs, bias_r, bhm, bhs, bias_h, cb);
    copy_kernel<<<(n4 + 255) / 256, 256>>>(x, h, n4);

    for (int layer = 0; layer < 3; layer++) {
        // K1 (A=h): t = h@Wa ; zp = h@Wzs + cbz ; rp = h@Wrs + cbr
        {
            GemmParams p{};
            p.o[0] = { Wa,  nullptr, nullptr, nullptr, t, 0 };
            p.o[1] = { Wzs, cbz,     nullptr, nullptr, z, 0 };
            p.o[2] = { Wrs, cbr,     nullptr, nullptr, r, 0 };
            gemm_fused<3><<<gg64, 256, GEMM_SMEM_BYTES>>>(h, p, N);
        }
        // m = t (self loops), then m[dst] += t[src]*ew
        copy_kernel<<<(n4 + 255) / 256, 256>>>(t, m, n4);
        {
            long long work = (long long)E * 32;
            scatter_kernel<<<(unsigned)((work + 255) / 256), 256>>>(ei, ew, t, m, E);
        }
        // K2 (A=m): z = sig(m@Wzm + zp) ; rh = sig(m@Wrm + rp)*h ; ci = m@Whm + cbh
        {
            GemmParams p{};
            p.o[0] = { Wzm, nullptr, z, nullptr, z,  1 };
            p.o[1] = { Wrm, nullptr, r, h,       r,  2 };
            p.o[2] = { Whm, cbh,     nullptr, nullptr, ci, 0 };
            gemm_fused<3><<<gg64, 256, GEMM_SMEM_BYTES>>>(m, p, N);
        }
        // K3 (A=rh): ci += rh@Whs
        {
            GemmParams p{};
            p.o[0] = { Whs, nullptr, nullptr, nullptr, ci, 3 };
            gemm_fused<1><<<gg64, 256, GEMM_SMEM_BYTES>>>(r, p, N);
        }
        // K4 (A=ci): g1 = ci@Whl + bhl ; h = z*(g1*sig(ci@Whg + bhg)) + (1-z)*h
        {
            GemmParams p{};
            p.o[0] = { Whl, bhl, nullptr, nullptr, gg, 0 };
            p.o[1] = { Whg, bhg, gg,      z,       h,  4 };
            gemm_fused<2><<<gg64, 256, GEMM_SMEM_BYTES>>>(ci, p, N);
        }
    }

    // attention gate: t = h * sigmoid(h @ Wag + bag)
    {
        long long work = (long long)N * 32;
        att_kernel<<<(unsigned)((work + 255) / 256), 256>>>(h, Wag, bag, t, N);
    }
    // m = relu(t @ Wae + bae)
    {
        GemmParams p{};
        p.o[0] = { Wae, bae, nullptr, nullptr, m, 5 };
        gemm_fused<1><<<gg64, 256, GEMM_SMEM_BYTES>>>(t, p, N);
    }

    // pooling + MLP head
    zero_pool_kernel<<<(NGRAPH * D + 255) / 256, 256>>>(pmax, psum, cnt);
    {
        long long work = (long long)N * 32;
        pool_kernel<<<(unsigned)((work + 255) / 256), 256>>>(m, batch, pmax, psum, cnt, N);
    }
    mlp_kernel<<<NGRAPH, D>>>(pmax, psum, cnt, W1, b1, W2, b2, out);
}